// round 2
// baseline (speedup 1.0000x reference)
#include <cuda_runtime.h>

#define EPS 1e-5f

// ---------------- scratch (static device globals; no allocations) ----------------
__device__ float g_agg[61952 * 256];
__device__ float g_tgt[61952 * 256];
__device__ float g_h[61952 * 256];
__device__ float g_x1[61952 * 256];
__device__ float g_x2[5632 * 256];
__device__ float g_x3[512 * 256];
__device__ float g_psum[484 * 256];
__device__ float g_psumsq[484 * 256];
__device__ float g_scale[256];
__device__ float g_shift[256];

// ---------------- kernel 1: gather + mean (FANOUT=10 contiguous edges per target) + target gather
__global__ void gather_mean_kernel(const float* __restrict__ x,
                                   const int* __restrict__ src,
                                   const int* __restrict__ tlid,
                                   float* __restrict__ agg,
                                   float* __restrict__ tgt) {
    const int grp  = threadIdx.x >> 6;   // 4 targets per block
    const int lane = threadIdx.x & 63;   // 64 float4s per 256-float row
    const int t    = blockIdx.x * 4 + grp;
    const float4* x4 = (const float4*)x;

    int base = t * 10;
    int idx[10];
#pragma unroll
    for (int j = 0; j < 10; j++) idx[j] = src[base + j];

    float4 acc = make_float4(0.f, 0.f, 0.f, 0.f);
#pragma unroll
    for (int j = 0; j < 10; j++) {
        float4 v = x4[idx[j] * 64 + lane];
        acc.x += v.x; acc.y += v.y; acc.z += v.z; acc.w += v.w;
    }
    acc.x *= 0.1f; acc.y *= 0.1f; acc.z *= 0.1f; acc.w *= 0.1f;
    ((float4*)agg)[t * 64 + lane] = acc;

    ((float4*)tgt)[t * 64 + lane] = x4[tlid[t] * 64 + lane];
}

// ---------------- kernel 2: H = agg@Wl + tgt@Wr + b   (M x 256, K=256 each half)
__global__ void __launch_bounds__(256) gemm_dual_kernel(
    const float* __restrict__ A1, const float* __restrict__ A2,
    const float* __restrict__ W1, const float* __restrict__ W2,
    const float* __restrict__ bias, float* __restrict__ H) {
    __shared__ float As[8][132];
    __shared__ float Ws[8][128];

    const int tid  = threadIdx.x;
    const int tx   = tid & 15;
    const int ty   = tid >> 4;
    const int row0 = blockIdx.y * 128;
    const int col0 = blockIdx.x * 128;

    const int arow = tid >> 1;        // 0..127
    const int ak   = (tid & 1) * 4;   // 0 / 4
    const int wr   = tid >> 5;        // 0..7
    const int wc   = (tid & 31) * 4;  // 0..124

    float acc[8][8];
#pragma unroll
    for (int i = 0; i < 8; i++)
#pragma unroll
        for (int j = 0; j < 8; j++) acc[i][j] = 0.f;

#pragma unroll 1
    for (int half = 0; half < 2; half++) {
        const float* Ap = half ? A2 : A1;
        const float* Wp = half ? W2 : W1;
#pragma unroll 1
        for (int kb = 0; kb < 256; kb += 8) {
            float4 av = *(const float4*)&Ap[(row0 + arow) * 256 + kb + ak];
            As[ak + 0][arow] = av.x;
            As[ak + 1][arow] = av.y;
            As[ak + 2][arow] = av.z;
            As[ak + 3][arow] = av.w;
            float4 wv = *(const float4*)&Wp[(kb + wr) * 256 + col0 + wc];
            *(float4*)&Ws[wr][wc] = wv;
            __syncthreads();
#pragma unroll
            for (int k = 0; k < 8; k++) {
                float a[8], b[8];
#pragma unroll
                for (int i = 0; i < 8; i++) a[i] = As[k][ty * 8 + i];
#pragma unroll
                for (int j = 0; j < 8; j++) b[j] = Ws[k][tx * 8 + j];
#pragma unroll
                for (int i = 0; i < 8; i++)
#pragma unroll
                    for (int j = 0; j < 8; j++) acc[i][j] += a[i] * b[j];
            }
            __syncthreads();
        }
    }

#pragma unroll
    for (int i = 0; i < 8; i++) {
        int r = row0 + ty * 8 + i;
#pragma unroll
        for (int j = 0; j < 8; j += 4) {
            int c = col0 + tx * 8 + j;
            float4 o;
            o.x = acc[i][j + 0] + bias[c + 0];
            o.y = acc[i][j + 1] + bias[c + 1];
            o.z = acc[i][j + 2] + bias[c + 2];
            o.w = acc[i][j + 3] + bias[c + 3];
            *(float4*)&H[r * 256 + c] = o;
        }
    }
}

// ---------------- kernel 3: per-block column partial sums / sumsq (deterministic, no atomics)
__global__ void bn_partial_kernel(const float* __restrict__ H, int M) {
    const int col = threadIdx.x;
    float s = 0.f, ss = 0.f;
    for (int row = blockIdx.x; row < M; row += gridDim.x) {
        float v = H[row * 256 + col];
        s += v;
        ss += v * v;
    }
    g_psum[blockIdx.x * 256 + col]   = s;
    g_psumsq[blockIdx.x * 256 + col] = ss;
}

// ---------------- kernel 4: finalize BN affine (scale/shift)
__global__ void bn_finalize_kernel(const float* __restrict__ gam,
                                   const float* __restrict__ beta,
                                   int M, int NB) {
    const int col = threadIdx.x;
    float s = 0.f, ss = 0.f;
    for (int b = 0; b < NB; b++) {
        s  += g_psum[b * 256 + col];
        ss += g_psumsq[b * 256 + col];
    }
    float inv_m = 1.f / (float)M;
    float mu  = s * inv_m;
    float var = ss * inv_m - mu * mu;
    float inv = rsqrtf(var + EPS);
    float sc  = gam[col] * inv;
    g_scale[col] = sc;
    g_shift[col] = beta[col] - mu * sc;
}

// ---------------- kernel 5: x = relu(h * scale + shift)
__global__ void bn_apply_kernel(const float* __restrict__ H, float* __restrict__ X) {
    const int idx = blockIdx.x * blockDim.x + threadIdx.x;  // over M*64 float4
    const int c4  = idx & 63;
    float4 h  = ((const float4*)H)[idx];
    float4 sc = ((const float4*)g_scale)[c4];
    float4 sh = ((const float4*)g_shift)[c4];
    float4 o;
    o.x = fmaxf(0.f, h.x * sc.x + sh.x);
    o.y = fmaxf(0.f, h.y * sc.y + sh.y);
    o.z = fmaxf(0.f, h.z * sc.z + sh.z);
    o.w = fmaxf(0.f, h.w * sc.w + sh.w);
    ((float4*)X)[idx] = o;
}

// ---------------- kernel 6: out = x3 @ fc_w + fc_b   ([512,256]@[256,47])
__global__ void fc_kernel(const float* __restrict__ X, const float* __restrict__ W,
                          const float* __restrict__ b, float* __restrict__ out) {
    __shared__ float xs[256];
    const int row = blockIdx.x;
    xs[threadIdx.x] = X[row * 256 + threadIdx.x];
    __syncthreads();
    const int c = threadIdx.x;
    if (c < 47) {
        float acc = b[c];
#pragma unroll 8
        for (int k = 0; k < 256; k++) acc += xs[k] * W[k * 47 + c];
        out[row * 47 + c] = acc;
    }
}

// ---------------- host ----------------
extern "C" void kernel_launch(void* const* d_in, const int* in_sizes, int n_in,
                              void* d_out, int out_size) {
    // Resolve input ordering: signature order vs setup-dict order.
    // Signature: idx4 = src1 (56320). Dict: idx4 = Wl0 (65536).
    const bool dict_order = (in_sizes[4] == 65536);

    const float* x_feat = (const float*)d_in[0];
    const int *src[3], *tlid[3];
    const float *Wl[3], *Wr[3], *bb[3], *gam[3], *bet[3];
    if (dict_order) {
        for (int i = 0; i < 3; i++) {
            int base = 1 + i * 8;
            src[i]  = (const int*)d_in[base + 0];
            tlid[i] = (const int*)d_in[base + 2];
            Wl[i]   = (const float*)d_in[base + 3];
            Wr[i]   = (const float*)d_in[base + 4];
            bb[i]   = (const float*)d_in[base + 5];
            gam[i]  = (const float*)d_in[base + 6];
            bet[i]  = (const float*)d_in[base + 7];
        }
    } else {
        for (int i = 0; i < 3; i++) {
            src[i]  = (const int*)d_in[1 + i * 3];
            tlid[i] = (const int*)d_in[3 + i * 3];
            Wl[i]   = (const float*)d_in[10 + i * 5];
            Wr[i]   = (const float*)d_in[11 + i * 5];
            bb[i]   = (const float*)d_in[12 + i * 5];
            gam[i]  = (const float*)d_in[13 + i * 5];
            bet[i]  = (const float*)d_in[14 + i * 5];
        }
    }
    const float* fc_w = (const float*)d_in[25];
    const float* fc_b = (const float*)d_in[26];
    float* out = (float*)d_out;

    static float *agg = nullptr, *tgt = nullptr, *hb = nullptr;
    static float *x1 = nullptr, *x2 = nullptr, *x3 = nullptr;
    if (!agg) {
        cudaGetSymbolAddress((void**)&agg, g_agg);
        cudaGetSymbolAddress((void**)&tgt, g_tgt);
        cudaGetSymbolAddress((void**)&hb,  g_h);
        cudaGetSymbolAddress((void**)&x1,  g_x1);
        cudaGetSymbolAddress((void**)&x2,  g_x2);
        cudaGetSymbolAddress((void**)&x3,  g_x3);
    }

    const int NT[3] = {61952, 5632, 512};
    const int NB[3] = {484, 44, 4};
    const float* xin = x_feat;
    float* xout[3] = {x1, x2, x3};

    for (int i = 0; i < 3; i++) {
        const int T = NT[i];
        gather_mean_kernel<<<T / 4, 256>>>(xin, src[i], tlid[i], agg, tgt);
        dim3 gdim(2, T / 128);
        gemm_dual_kernel<<<gdim, 256>>>(agg, tgt, Wl[i], Wr[i], bb[i], hb);
        bn_partial_kernel<<<NB[i], 256>>>(hb, T);
        bn_finalize_kernel<<<1, 256>>>(gam[i], bet[i], T, NB[i]);
        bn_apply_kernel<<<T / 4, 256>>>(hb, xout[i]);
        xin = xout[i];
    }
    fc_kernel<<<512, 256>>>(x3, fc_w, fc_b, out);
}

// round 9
// speedup vs baseline: 1.8342x; 1.8342x over previous
#include <cuda_runtime.h>
#include <cuda_bf16.h>
#include <cstdint>

#define EPS 1e-5f

// ---------------- scratch (static device globals; no allocations) ----------------
__device__ __nv_bfloat16 g_Ah[61952 * 512];   // [T, 512] = [agg | tgt], bf16 hi
__device__ __nv_bfloat16 g_Al[61952 * 512];   // bf16 lo residual
__device__ __nv_bfloat16 g_Bh[256 * 512];     // W^T stacked [N=256, K=512], hi
__device__ __nv_bfloat16 g_Bl[256 * 512];     // lo
__device__ float g_h[61952 * 256];
__device__ float g_x1[61952 * 256];
__device__ float g_x2[5632 * 256];
__device__ float g_x3[512 * 256];
__device__ float g_psum[484 * 256];
__device__ float g_psumsq[484 * 256];
__device__ float g_scale[256];
__device__ float g_shift[256];

// ---------------- helpers ----------------
__device__ __forceinline__ uint32_t smem_u32(const void* p) {
    uint32_t a;
    asm("{ .reg .u64 t; cvta.to.shared.u64 t, %1; cvt.u32.u64 %0, t; }" : "=r"(a) : "l"(p));
    return a;
}
__device__ __forceinline__ void ldsm4(uint32_t& r0, uint32_t& r1, uint32_t& r2, uint32_t& r3,
                                      uint32_t addr) {
    asm volatile("ldmatrix.sync.aligned.m8n8.x4.shared.b16 {%0,%1,%2,%3}, [%4];"
                 : "=r"(r0), "=r"(r1), "=r"(r2), "=r"(r3) : "r"(addr));
}
__device__ __forceinline__ void mma_bf16(float* d, const uint32_t* a, uint32_t b0, uint32_t b1) {
    asm volatile(
        "mma.sync.aligned.m16n8k16.row.col.f32.bf16.bf16.f32 "
        "{%0,%1,%2,%3}, {%4,%5,%6,%7}, {%8,%9}, {%0,%1,%2,%3};"
        : "+f"(d[0]), "+f"(d[1]), "+f"(d[2]), "+f"(d[3])
        : "r"(a[0]), "r"(a[1]), "r"(a[2]), "r"(a[3]), "r"(b0), "r"(b1));
}
// SW64 swizzle for 64-byte rows (Swizzle over bits[4:5] ^= bits[7:8])
__device__ __forceinline__ uint32_t sw64(uint32_t off) {
    return off ^ ((off >> 3) & 0x30);
}

// ---------------- kernel 1: gather + mean + target gather, emit split bf16 A ----------------
__device__ __forceinline__ void split_store(__nv_bfloat16* ph, __nv_bfloat16* pl, float4 v) {
    __nv_bfloat16 h0 = __float2bfloat16(v.x), h1 = __float2bfloat16(v.y),
                  h2 = __float2bfloat16(v.z), h3 = __float2bfloat16(v.w);
    __nv_bfloat16 l0 = __float2bfloat16(v.x - __bfloat162float(h0));
    __nv_bfloat16 l1 = __float2bfloat16(v.y - __bfloat162float(h1));
    __nv_bfloat16 l2 = __float2bfloat16(v.z - __bfloat162float(h2));
    __nv_bfloat16 l3 = __float2bfloat16(v.w - __bfloat162float(h3));
    *(ushort4*)ph = make_ushort4(__bfloat16_as_ushort(h0), __bfloat16_as_ushort(h1),
                                 __bfloat16_as_ushort(h2), __bfloat16_as_ushort(h3));
    *(ushort4*)pl = make_ushort4(__bfloat16_as_ushort(l0), __bfloat16_as_ushort(l1),
                                 __bfloat16_as_ushort(l2), __bfloat16_as_ushort(l3));
}

__global__ void gather_mean_kernel(const float* __restrict__ x,
                                   const int* __restrict__ src,
                                   const int* __restrict__ tlid,
                                   __nv_bfloat16* __restrict__ Ah,
                                   __nv_bfloat16* __restrict__ Al) {
    const int grp  = threadIdx.x >> 6;
    const int lane = threadIdx.x & 63;
    const int t    = blockIdx.x * 4 + grp;
    const float4* x4 = (const float4*)x;

    int base = t * 10;
    int idx[10];
#pragma unroll
    for (int j = 0; j < 10; j++) idx[j] = src[base + j];

    float4 acc = make_float4(0.f, 0.f, 0.f, 0.f);
#pragma unroll
    for (int j = 0; j < 10; j++) {
        float4 v = x4[(size_t)idx[j] * 64 + lane];
        acc.x += v.x; acc.y += v.y; acc.z += v.z; acc.w += v.w;
    }
    acc.x *= 0.1f; acc.y *= 0.1f; acc.z *= 0.1f; acc.w *= 0.1f;

    size_t ob = (size_t)t * 512 + lane * 4;
    split_store(Ah + ob, Al + ob, acc);                   // agg -> K cols [0,256)
    float4 tv = x4[(size_t)tlid[t] * 64 + lane];
    split_store(Ah + ob + 256, Al + ob + 256, tv);        // tgt -> K cols [256,512)
}

// ---------------- kernel 2: W transpose+split: B[n][k] = (k<256 ? Wl[k][n] : Wr[k-256][n]) ----
__global__ void conv_w_kernel(const float* __restrict__ Wl, const float* __restrict__ Wr,
                              __nv_bfloat16* __restrict__ Bh, __nv_bfloat16* __restrict__ Bl) {
    int idx = blockIdx.x * 256 + threadIdx.x;    // 131072 total
    int n = idx >> 9, k = idx & 511;
    float v = (k < 256) ? Wl[k * 256 + n] : Wr[(k - 256) * 256 + n];
    __nv_bfloat16 h = __float2bfloat16(v);
    Bh[idx] = h;
    Bl[idx] = __float2bfloat16(v - __bfloat162float(h));
}

// ---------------- kernel 3: mma.sync GEMM  H[M,256] = Ah*Bh^T + Al*Bh^T + Ah*Bl^T + bias ----
// BM=128 BN=128 BK=32, 256 threads, warp grid 2x4, warp tile 64x32.
// Static smem: 4 tiles x 128x32 bf16 = 4 x 8KB = 32KB (no opt-in needed).
__global__ void __launch_bounds__(256) gemm_mma_kernel(
    const __nv_bfloat16* __restrict__ Ah, const __nv_bfloat16* __restrict__ Al,
    const __nv_bfloat16* __restrict__ Bh, const __nv_bfloat16* __restrict__ Bl,
    const float* __restrict__ bias, float* __restrict__ H) {
    __shared__ __align__(128) char sAh[8192];
    __shared__ __align__(128) char sAl[8192];
    __shared__ __align__(128) char sBh[8192];
    __shared__ __align__(128) char sBl[8192];

    const int tid  = threadIdx.x;
    const int lane = tid & 31;
    const int wid  = tid >> 5;
    const int wm   = wid >> 2;        // 0..1   (64 rows)
    const int wn   = wid & 3;         // 0..3   (32 cols)
    const int row0 = blockIdx.y * 128;
    const int col0 = blockIdx.x * 128;

    const uint32_t uAh = smem_u32(sAh), uAl = smem_u32(sAl);
    const uint32_t uBh = smem_u32(sBh), uBl = smem_u32(sBl);

    float acc[4][4][4];
#pragma unroll
    for (int mt = 0; mt < 4; mt++)
#pragma unroll
        for (int nt = 0; nt < 4; nt++)
#pragma unroll
            for (int r = 0; r < 4; r++) acc[mt][nt][r] = 0.f;

    // global->smem: each row is 64B = 4 uint4; thread t loads 2 uint4 of row t>>1
    const int grow = tid >> 1;            // 0..127
    const int gch  = (tid & 1) * 2;       // uint4 chunk 0 or 2

    // ldmatrix per-lane address parts
    const int a_r = (lane & 7) + ((lane & 8) ? 8 : 0);   // m-row within 16
    const int a_k = (lane & 16) ? 8 : 0;                 // k-col within 16
    const int b_r = (lane & 7) + ((lane & 16) ? 8 : 0);  // n-row within 16
    const int b_k = (lane & 8) ? 8 : 0;

#pragma unroll 1
    for (int kb = 0; kb < 16; kb++) {
        // ---- load A(128x32 hi/lo) and B(128x32 hi/lo) tiles, SW64 swizzled ----
        {
            const uint4* pah = (const uint4*)(Ah + (size_t)(row0 + grow) * 512 + kb * 32);
            const uint4* pal = (const uint4*)(Al + (size_t)(row0 + grow) * 512 + kb * 32);
            const uint4* pbh = (const uint4*)(Bh + (size_t)(col0 + grow) * 512 + kb * 32);
            const uint4* pbl = (const uint4*)(Bl + (size_t)(col0 + grow) * 512 + kb * 32);
#pragma unroll
            for (int i = 0; i < 2; i++) {
                uint32_t off = grow * 64 + (gch + i) * 16;
                uint32_t sw = sw64(off);
                *(uint4*)(sAh + sw) = pah[gch + i];
                *(uint4*)(sAl + sw) = pal[gch + i];
                *(uint4*)(sBh + sw) = pbh[gch + i];
                *(uint4*)(sBl + sw) = pbl[gch + i];
            }
        }
        __syncthreads();

#pragma unroll
        for (int ks = 0; ks < 2; ks++) {
            uint32_t ah[4][4], al[4][4];
#pragma unroll
            for (int mt = 0; mt < 4; mt++) {
                uint32_t off = (wm * 64 + mt * 16 + a_r) * 64 + (ks * 16 + a_k) * 2;
                uint32_t sw = sw64(off);
                ldsm4(ah[mt][0], ah[mt][1], ah[mt][2], ah[mt][3], uAh + sw);
                ldsm4(al[mt][0], al[mt][1], al[mt][2], al[mt][3], uAl + sw);
            }
            uint32_t bh[2][4], bl[2][4];
#pragma unroll
            for (int np = 0; np < 2; np++) {
                uint32_t off = (wn * 32 + np * 16 + b_r) * 64 + (ks * 16 + b_k) * 2;
                uint32_t sw = sw64(off);
                ldsm4(bh[np][0], bh[np][1], bh[np][2], bh[np][3], uBh + sw);
                ldsm4(bl[np][0], bl[np][1], bl[np][2], bl[np][3], uBl + sw);
            }
#pragma unroll
            for (int mt = 0; mt < 4; mt++)
#pragma unroll
                for (int nt = 0; nt < 4; nt++) {
                    uint32_t b0h = bh[nt >> 1][(nt & 1) * 2];
                    uint32_t b1h = bh[nt >> 1][(nt & 1) * 2 + 1];
                    uint32_t b0l = bl[nt >> 1][(nt & 1) * 2];
                    uint32_t b1l = bl[nt >> 1][(nt & 1) * 2 + 1];
                    mma_bf16(acc[mt][nt], ah[mt], b0h, b1h);   // Ah*Bh
                    mma_bf16(acc[mt][nt], al[mt], b0h, b1h);   // Al*Bh
                    mma_bf16(acc[mt][nt], ah[mt], b0l, b1l);   // Ah*Bl
                }
        }
        __syncthreads();
    }

    // ---- epilogue: add bias, write H ----
#pragma unroll
    for (int mt = 0; mt < 4; mt++) {
        int r0 = row0 + wm * 64 + mt * 16 + (lane >> 2);
#pragma unroll
        for (int nt = 0; nt < 4; nt++) {
            int c = col0 + wn * 32 + nt * 8 + (lane & 3) * 2;
            float b0 = bias[c], b1 = bias[c + 1];
            *(float2*)&H[(size_t)r0 * 256 + c] =
                make_float2(acc[mt][nt][0] + b0, acc[mt][nt][1] + b1);
            *(float2*)&H[(size_t)(r0 + 8) * 256 + c] =
                make_float2(acc[mt][nt][2] + b0, acc[mt][nt][3] + b1);
        }
    }
}

// ---------------- kernel 4: per-block column partial sums / sumsq (deterministic) -----------
__global__ void bn_partial_kernel(const float* __restrict__ H, int M) {
    const int col = threadIdx.x;
    float s = 0.f, ss = 0.f;
    for (int row = blockIdx.x; row < M; row += gridDim.x) {
        float v = H[(size_t)row * 256 + col];
        s += v;
        ss += v * v;
    }
    g_psum[blockIdx.x * 256 + col]   = s;
    g_psumsq[blockIdx.x * 256 + col] = ss;
}

// ---------------- kernel 5: finalize BN affine (parallel: one block per column) -------------
__global__ void bn_finalize_kernel(const float* __restrict__ gam,
                                   const float* __restrict__ beta,
                                   int M, int NB) {
    const int col = blockIdx.x;
    const int t = threadIdx.x;
    float s = 0.f, ss = 0.f;
    for (int i = t; i < NB; i += 128) {
        s  += g_psum[i * 256 + col];
        ss += g_psumsq[i * 256 + col];
    }
    __shared__ float shs[128], shq[128];
    shs[t] = s; shq[t] = ss;
    __syncthreads();
    for (int o = 64; o > 0; o >>= 1) {
        if (t < o) { shs[t] += shs[t + o]; shq[t] += shq[t + o]; }
        __syncthreads();
    }
    if (t == 0) {
        float inv_m = 1.f / (float)M;
        float mu  = shs[0] * inv_m;
        float var = shq[0] * inv_m - mu * mu;
        float inv = rsqrtf(var + EPS);
        float sc  = gam[col] * inv;
        g_scale[col] = sc;
        g_shift[col] = beta[col] - mu * sc;
    }
}

// ---------------- kernel 6: x = relu(h * scale + shift) ----------------
__global__ void bn_apply_kernel(const float* __restrict__ H, float* __restrict__ X) {
    const int idx = blockIdx.x * blockDim.x + threadIdx.x;
    const int c4  = idx & 63;
    float4 h  = ((const float4*)H)[idx];
    float4 sc = ((const float4*)g_scale)[c4];
    float4 sh = ((const float4*)g_shift)[c4];
    float4 o;
    o.x = fmaxf(0.f, h.x * sc.x + sh.x);
    o.y = fmaxf(0.f, h.y * sc.y + sh.y);
    o.z = fmaxf(0.f, h.z * sc.z + sh.z);
    o.w = fmaxf(0.f, h.w * sc.w + sh.w);
    ((float4*)X)[idx] = o;
}

// ---------------- kernel 7: out = x3 @ fc_w + fc_b   ([512,256]@[256,47]) -------------------
__global__ void fc_kernel(const float* __restrict__ X, const float* __restrict__ W,
                          const float* __restrict__ b, float* __restrict__ out) {
    __shared__ float xs[256];
    const int row = blockIdx.x;
    xs[threadIdx.x] = X[row * 256 + threadIdx.x];
    __syncthreads();
    const int c = threadIdx.x;
    if (c < 47) {
        float acc = b[c];
#pragma unroll 8
        for (int k = 0; k < 256; k++) acc += xs[k] * W[k * 47 + c];
        out[row * 47 + c] = acc;
    }
}

// ---------------- host ----------------
extern "C" void kernel_launch(void* const* d_in, const int* in_sizes, int n_in,
                              void* d_out, int out_size) {
    const bool dict_order = (in_sizes[4] == 65536);

    const float* x_feat = (const float*)d_in[0];
    const int *src[3], *tlid[3];
    const float *Wl[3], *Wr[3], *bb[3], *gam[3], *bet[3];
    if (dict_order) {
        for (int i = 0; i < 3; i++) {
            int base = 1 + i * 8;
            src[i]  = (const int*)d_in[base + 0];
            tlid[i] = (const int*)d_in[base + 2];
            Wl[i]   = (const float*)d_in[base + 3];
            Wr[i]   = (const float*)d_in[base + 4];
            bb[i]   = (const float*)d_in[base + 5];
            gam[i]  = (const float*)d_in[base + 6];
            bet[i]  = (const float*)d_in[base + 7];
        }
    } else {
        for (int i = 0; i < 3; i++) {
            src[i]  = (const int*)d_in[1 + i * 3];
            tlid[i] = (const int*)d_in[3 + i * 3];
            Wl[i]   = (const float*)d_in[10 + i * 5];
            Wr[i]   = (const float*)d_in[11 + i * 5];
            bb[i]   = (const float*)d_in[12 + i * 5];
            gam[i]  = (const float*)d_in[13 + i * 5];
            bet[i]  = (const float*)d_in[14 + i * 5];
        }
    }
    const float* fc_w = (const float*)d_in[25];
    const float* fc_b = (const float*)d_in[26];
    float* out = (float*)d_out;

    // Pure address queries (capture-safe, no caching / static guards)
    __nv_bfloat16 *Ahp, *Alp, *Bhp, *Blp;
    float *hb, *x1, *x2, *x3;
    cudaGetSymbolAddress((void**)&Ahp, g_Ah);
    cudaGetSymbolAddress((void**)&Alp, g_Al);
    cudaGetSymbolAddress((void**)&Bhp, g_Bh);
    cudaGetSymbolAddress((void**)&Blp, g_Bl);
    cudaGetSymbolAddress((void**)&hb,  g_h);
    cudaGetSymbolAddress((void**)&x1,  g_x1);
    cudaGetSymbolAddress((void**)&x2,  g_x2);
    cudaGetSymbolAddress((void**)&x3,  g_x3);

    const int NT[3] = {61952, 5632, 512};
    const int NB[3] = {484, 44, 4};
    const float* xin = x_feat;
    float* xout[3] = {x1, x2, x3};

    for (int i = 0; i < 3; i++) {
        const int T = NT[i];
        conv_w_kernel<<<512, 256>>>(Wl[i], Wr[i], Bhp, Blp);
        gather_mean_kernel<<<T / 4, 256>>>(xin, src[i], tlid[i], Ahp, Alp);
        dim3 gdim(2, T / 128);
        gemm_mma_kernel<<<gdim, 256>>>(Ahp, Alp, Bhp, Blp, bb[i], hb);
        bn_partial_kernel<<<NB[i], 256>>>(hb, T);
        bn_finalize_kernel<<<256, 128>>>(gam[i], bet[i], T, NB[i]);
        bn_apply_kernel<<<T / 4, 256>>>(hb, xout[i]);
        xin = xout[i];
    }
    fc_kernel<<<512, 256>>>(x3, fc_w, fc_b, out);
}

// round 11
// speedup vs baseline: 2.3510x; 1.2817x over previous
#include <cuda_runtime.h>
#include <cuda_bf16.h>
#include <cstdint>

#define EPS 1e-5f

// ---------------- scratch (static device globals; no allocations) ----------------
__device__ __nv_bfloat16 g_Ah[61952 * 512];   // [T, 512] = [agg | tgt], bf16 hi
__device__ __nv_bfloat16 g_Al[61952 * 512];   // bf16 lo residual
__device__ __nv_bfloat16 g_Bh[256 * 512];     // W^T stacked [N=256, K=512], hi
__device__ __nv_bfloat16 g_Bl[256 * 512];     // lo
__device__ float g_h[61952 * 256];
__device__ float g_psum[484 * 256];
__device__ float g_psumsq[484 * 256];
__device__ float g_scale[256];
__device__ float g_shift[256];

// ---------------- helpers ----------------
__device__ __forceinline__ uint32_t smem_u32(const void* p) {
    uint32_t a;
    asm("{ .reg .u64 t; cvta.to.shared.u64 t, %1; cvt.u32.u64 %0, t; }" : "=r"(a) : "l"(p));
    return a;
}
__device__ __forceinline__ void ldsm4(uint32_t& r0, uint32_t& r1, uint32_t& r2, uint32_t& r3,
                                      uint32_t addr) {
    asm volatile("ldmatrix.sync.aligned.m8n8.x4.shared.b16 {%0,%1,%2,%3}, [%4];"
                 : "=r"(r0), "=r"(r1), "=r"(r2), "=r"(r3) : "r"(addr));
}
__device__ __forceinline__ void mma_bf16(float* d, const uint32_t* a, uint32_t b0, uint32_t b1) {
    asm volatile(
        "mma.sync.aligned.m16n8k16.row.col.f32.bf16.bf16.f32 "
        "{%0,%1,%2,%3}, {%4,%5,%6,%7}, {%8,%9}, {%0,%1,%2,%3};"
        : "+f"(d[0]), "+f"(d[1]), "+f"(d[2]), "+f"(d[3])
        : "r"(a[0]), "r"(a[1]), "r"(a[2]), "r"(a[3]), "r"(b0), "r"(b1));
}
// SW64 swizzle for 64-byte rows
__device__ __forceinline__ uint32_t sw64(uint32_t off) {
    return off ^ ((off >> 3) & 0x30);
}

// ---------------- kernel 1: gather + mean + target gather (+ fused BN-apply of prev layer) --
__device__ __forceinline__ void split_store(__nv_bfloat16* ph, __nv_bfloat16* pl, float4 v) {
    __nv_bfloat16 h0 = __float2bfloat16(v.x), h1 = __float2bfloat16(v.y),
                  h2 = __float2bfloat16(v.z), h3 = __float2bfloat16(v.w);
    __nv_bfloat16 l0 = __float2bfloat16(v.x - __bfloat162float(h0));
    __nv_bfloat16 l1 = __float2bfloat16(v.y - __bfloat162float(h1));
    __nv_bfloat16 l2 = __float2bfloat16(v.z - __bfloat162float(h2));
    __nv_bfloat16 l3 = __float2bfloat16(v.w - __bfloat162float(h3));
    *(ushort4*)ph = make_ushort4(__bfloat16_as_ushort(h0), __bfloat16_as_ushort(h1),
                                 __bfloat16_as_ushort(h2), __bfloat16_as_ushort(h3));
    *(ushort4*)pl = make_ushort4(__bfloat16_as_ushort(l0), __bfloat16_as_ushort(l1),
                                 __bfloat16_as_ushort(l2), __bfloat16_as_ushort(l3));
}

__global__ void gather_mean_kernel(const float* __restrict__ x,
                                   const int* __restrict__ src,
                                   const int* __restrict__ tlid,
                                   __nv_bfloat16* __restrict__ Ah,
                                   __nv_bfloat16* __restrict__ Al,
                                   int affine) {
    const int grp  = threadIdx.x >> 6;
    const int lane = threadIdx.x & 63;
    const int t    = blockIdx.x * 4 + grp;
    const float4* x4 = (const float4*)x;

    float4 sc = make_float4(1.f, 1.f, 1.f, 1.f);
    float4 sh = make_float4(0.f, 0.f, 0.f, 0.f);
    if (affine) {
        sc = ((const float4*)g_scale)[lane];
        sh = ((const float4*)g_shift)[lane];
    }

    int base = t * 10;
    int idx[10];
#pragma unroll
    for (int j = 0; j < 10; j++) idx[j] = src[base + j];

    float4 acc = make_float4(0.f, 0.f, 0.f, 0.f);
#pragma unroll
    for (int j = 0; j < 10; j++) {
        float4 v = x4[(size_t)idx[j] * 64 + lane];
        if (affine) {
            v.x = fmaxf(0.f, v.x * sc.x + sh.x);
            v.y = fmaxf(0.f, v.y * sc.y + sh.y);
            v.z = fmaxf(0.f, v.z * sc.z + sh.z);
            v.w = fmaxf(0.f, v.w * sc.w + sh.w);
        }
        acc.x += v.x; acc.y += v.y; acc.z += v.z; acc.w += v.w;
    }
    acc.x *= 0.1f; acc.y *= 0.1f; acc.z *= 0.1f; acc.w *= 0.1f;

    size_t ob = (size_t)t * 512 + lane * 4;
    split_store(Ah + ob, Al + ob, acc);                   // agg -> K cols [0,256)
    float4 tv = x4[(size_t)tlid[t] * 64 + lane];
    if (affine) {
        tv.x = fmaxf(0.f, tv.x * sc.x + sh.x);
        tv.y = fmaxf(0.f, tv.y * sc.y + sh.y);
        tv.z = fmaxf(0.f, tv.z * sc.z + sh.z);
        tv.w = fmaxf(0.f, tv.w * sc.w + sh.w);
    }
    split_store(Ah + ob + 256, Al + ob + 256, tv);        // tgt -> K cols [256,512)
}

// ---------------- kernel 2: W transpose+split ----------------
__global__ void conv_w_kernel(const float* __restrict__ Wl, const float* __restrict__ Wr,
                              __nv_bfloat16* __restrict__ Bh, __nv_bfloat16* __restrict__ Bl) {
    int idx = blockIdx.x * 256 + threadIdx.x;    // 131072 total
    int n = idx >> 9, k = idx & 511;
    float v = (k < 256) ? Wl[k * 256 + n] : Wr[(k - 256) * 256 + n];
    __nv_bfloat16 h = __float2bfloat16(v);
    Bh[idx] = h;
    Bl[idx] = __float2bfloat16(v - __bfloat162float(h));
}

// ---------------- kernel 3: mma.sync GEMM + fused BN partial stats ----------------
// BM=128 BN=128 BK=32, 256 threads, warp grid 2x4, warp tile 64x32. Static smem ~34KB.
__global__ void __launch_bounds__(256) gemm_mma_kernel(
    const __nv_bfloat16* __restrict__ Ah, const __nv_bfloat16* __restrict__ Al,
    const __nv_bfloat16* __restrict__ Bh, const __nv_bfloat16* __restrict__ Bl,
    const float* __restrict__ bias, float* __restrict__ H) {
    __shared__ __align__(128) char sAh[8192];
    __shared__ __align__(128) char sAl[8192];
    __shared__ __align__(128) char sBh[8192];
    __shared__ __align__(128) char sBl[8192];
    __shared__ float sm_s[2][128];
    __shared__ float sm_q[2][128];

    const int tid  = threadIdx.x;
    const int lane = tid & 31;
    const int wid  = tid >> 5;
    const int wm   = wid >> 2;        // 0..1   (64 rows)
    const int wn   = wid & 3;         // 0..3   (32 cols)
    const int row0 = blockIdx.y * 128;
    const int col0 = blockIdx.x * 128;

    const uint32_t uAh = smem_u32(sAh), uAl = smem_u32(sAl);
    const uint32_t uBh = smem_u32(sBh), uBl = smem_u32(sBl);

    float acc[4][4][4];
#pragma unroll
    for (int mt = 0; mt < 4; mt++)
#pragma unroll
        for (int nt = 0; nt < 4; nt++)
#pragma unroll
            for (int r = 0; r < 4; r++) acc[mt][nt][r] = 0.f;

    const int grow = tid >> 1;            // 0..127
    const int gch  = (tid & 1) * 2;       // uint4 chunk 0 or 2

    const int a_r = (lane & 7) + ((lane & 8) ? 8 : 0);
    const int a_k = (lane & 16) ? 8 : 0;
    const int b_r = (lane & 7) + ((lane & 16) ? 8 : 0);
    const int b_k = (lane & 8) ? 8 : 0;

#pragma unroll 1
    for (int kb = 0; kb < 16; kb++) {
        {
            const uint4* pah = (const uint4*)(Ah + (size_t)(row0 + grow) * 512 + kb * 32);
            const uint4* pal = (const uint4*)(Al + (size_t)(row0 + grow) * 512 + kb * 32);
            const uint4* pbh = (const uint4*)(Bh + (size_t)(col0 + grow) * 512 + kb * 32);
            const uint4* pbl = (const uint4*)(Bl + (size_t)(col0 + grow) * 512 + kb * 32);
#pragma unroll
            for (int i = 0; i < 2; i++) {
                uint32_t off = grow * 64 + (gch + i) * 16;
                uint32_t sw = sw64(off);
                *(uint4*)(sAh + sw) = pah[gch + i];
                *(uint4*)(sAl + sw) = pal[gch + i];
                *(uint4*)(sBh + sw) = pbh[gch + i];
                *(uint4*)(sBl + sw) = pbl[gch + i];
            }
        }
        __syncthreads();

#pragma unroll
        for (int ks = 0; ks < 2; ks++) {
            uint32_t ah[4][4], al[4][4];
#pragma unroll
            for (int mt = 0; mt < 4; mt++) {
                uint32_t off = (wm * 64 + mt * 16 + a_r) * 64 + (ks * 16 + a_k) * 2;
                uint32_t sw = sw64(off);
                ldsm4(ah[mt][0], ah[mt][1], ah[mt][2], ah[mt][3], uAh + sw);
                ldsm4(al[mt][0], al[mt][1], al[mt][2], al[mt][3], uAl + sw);
            }
            uint32_t bh[2][4], bl[2][4];
#pragma unroll
            for (int np = 0; np < 2; np++) {
                uint32_t off = (wn * 32 + np * 16 + b_r) * 64 + (ks * 16 + b_k) * 2;
                uint32_t sw = sw64(off);
                ldsm4(bh[np][0], bh[np][1], bh[np][2], bh[np][3], uBh + sw);
                ldsm4(bl[np][0], bl[np][1], bl[np][2], bl[np][3], uBl + sw);
            }
#pragma unroll
            for (int mt = 0; mt < 4; mt++)
#pragma unroll
                for (int nt = 0; nt < 4; nt++) {
                    uint32_t b0h = bh[nt >> 1][(nt & 1) * 2];
                    uint32_t b1h = bh[nt >> 1][(nt & 1) * 2 + 1];
                    uint32_t b0l = bl[nt >> 1][(nt & 1) * 2];
                    uint32_t b1l = bl[nt >> 1][(nt & 1) * 2 + 1];
                    mma_bf16(acc[mt][nt], ah[mt], b0h, b1h);   // Ah*Bh
                    mma_bf16(acc[mt][nt], al[mt], b0h, b1h);   // Al*Bh
                    mma_bf16(acc[mt][nt], ah[mt], b0l, b1l);   // Ah*Bl
                }
        }
        __syncthreads();
    }

    // ---- epilogue: add bias, write H, accumulate per-column stats ----
#pragma unroll
    for (int nt = 0; nt < 4; nt++) {
        int c = col0 + wn * 32 + nt * 8 + (lane & 3) * 2;
        float b0 = bias[c], b1 = bias[c + 1];
        float s0 = 0.f, s1 = 0.f, q0 = 0.f, q1 = 0.f;
#pragma unroll
        for (int mt = 0; mt < 4; mt++) {
            int r0 = row0 + wm * 64 + mt * 16 + (lane >> 2);
            float h0 = acc[mt][nt][0] + b0;
            float h1 = acc[mt][nt][1] + b1;
            float h2 = acc[mt][nt][2] + b0;
            float h3 = acc[mt][nt][3] + b1;
            *(float2*)&H[(size_t)r0 * 256 + c] = make_float2(h0, h1);
            *(float2*)&H[(size_t)(r0 + 8) * 256 + c] = make_float2(h2, h3);
            s0 += h0 + h2;  s1 += h1 + h3;
            q0 += h0 * h0 + h2 * h2;
            q1 += h1 * h1 + h3 * h3;
        }
        // reduce across the 8 row-lane groups (lane bits 2..4), deterministic
#pragma unroll
        for (int off = 4; off < 32; off <<= 1) {
            s0 += __shfl_xor_sync(0xFFFFFFFFu, s0, off);
            s1 += __shfl_xor_sync(0xFFFFFFFFu, s1, off);
            q0 += __shfl_xor_sync(0xFFFFFFFFu, q0, off);
            q1 += __shfl_xor_sync(0xFFFFFFFFu, q1, off);
        }
        if (lane < 4) {
            int cl = wn * 32 + nt * 8 + lane * 2;
            sm_s[wm][cl] = s0;  sm_s[wm][cl + 1] = s1;
            sm_q[wm][cl] = q0;  sm_q[wm][cl + 1] = q1;
        }
    }
    __syncthreads();
    if (tid < 128) {
        g_psum[blockIdx.y * 256 + col0 + tid]   = sm_s[0][tid] + sm_s[1][tid];
        g_psumsq[blockIdx.y * 256 + col0 + tid] = sm_q[0][tid] + sm_q[1][tid];
    }
}

// ---------------- kernel 4: finalize BN affine (one block per column) ----------------
__global__ void bn_finalize_kernel(const float* __restrict__ gam,
                                   const float* __restrict__ beta,
                                   int M, int NB) {
    const int col = blockIdx.x;
    const int t = threadIdx.x;
    float s = 0.f, ss = 0.f;
    for (int i = t; i < NB; i += 128) {
        s  += g_psum[i * 256 + col];
        ss += g_psumsq[i * 256 + col];
    }
    __shared__ float shs[128], shq[128];
    shs[t] = s; shq[t] = ss;
    __syncthreads();
    for (int o = 64; o > 0; o >>= 1) {
        if (t < o) { shs[t] += shs[t + o]; shq[t] += shq[t + o]; }
        __syncthreads();
    }
    if (t == 0) {
        float inv_m = 1.f / (float)M;
        float mu  = shs[0] * inv_m;
        float var = shq[0] * inv_m - mu * mu;
        float inv = rsqrtf(var + EPS);
        float sc  = gam[col] * inv;
        g_scale[col] = sc;
        g_shift[col] = beta[col] - mu * sc;
    }
}

// ---------------- kernel 5: out = relu(bn(H3)) @ fc_w + fc_b  ([512,256]@[256,47]) ---------
__global__ void fc_kernel(const float* __restrict__ Hx, const float* __restrict__ W,
                          const float* __restrict__ b, float* __restrict__ out) {
    __shared__ float xs[256];
    const int row = blockIdx.x;
    const int t = threadIdx.x;
    xs[t] = fmaxf(0.f, Hx[row * 256 + t] * g_scale[t] + g_shift[t]);
    __syncthreads();
    if (t < 47) {
        float acc = b[t];
#pragma unroll 8
        for (int k = 0; k < 256; k++) acc += xs[k] * W[k * 47 + t];
        out[row * 47 + t] = acc;
    }
}

// ---------------- host ----------------
extern "C" void kernel_launch(void* const* d_in, const int* in_sizes, int n_in,
                              void* d_out, int out_size) {
    const bool dict_order = (in_sizes[4] == 65536);

    const float* x_feat = (const float*)d_in[0];
    const int *src[3], *tlid[3];
    const float *Wl[3], *Wr[3], *bb[3], *gam[3], *bet[3];
    if (dict_order) {
        for (int i = 0; i < 3; i++) {
            int base = 1 + i * 8;
            src[i]  = (const int*)d_in[base + 0];
            tlid[i] = (const int*)d_in[base + 2];
            Wl[i]   = (const float*)d_in[base + 3];
            Wr[i]   = (const float*)d_in[base + 4];
            bb[i]   = (const float*)d_in[base + 5];
            gam[i]  = (const float*)d_in[base + 6];
            bet[i]  = (const float*)d_in[base + 7];
        }
    } else {
        for (int i = 0; i < 3; i++) {
            src[i]  = (const int*)d_in[1 + i * 3];
            tlid[i] = (const int*)d_in[3 + i * 3];
            Wl[i]   = (const float*)d_in[10 + i * 5];
            Wr[i]   = (const float*)d_in[11 + i * 5];
            bb[i]   = (const float*)d_in[12 + i * 5];
            gam[i]  = (const float*)d_in[13 + i * 5];
            bet[i]  = (const float*)d_in[14 + i * 5];
        }
    }
    const float* fc_w = (const float*)d_in[25];
    const float* fc_b = (const float*)d_in[26];
    float* out = (float*)d_out;

    __nv_bfloat16 *Ahp, *Alp, *Bhp, *Blp;
    float *hb;
    cudaGetSymbolAddress((void**)&Ahp, g_Ah);
    cudaGetSymbolAddress((void**)&Alp, g_Al);
    cudaGetSymbolAddress((void**)&Bhp, g_Bh);
    cudaGetSymbolAddress((void**)&Blp, g_Bl);
    cudaGetSymbolAddress((void**)&hb,  g_h);

    const int NT[3] = {61952, 5632, 512};
    const float* xin = x_feat;

    for (int i = 0; i < 3; i++) {
        const int T = NT[i];
        conv_w_kernel<<<512, 256>>>(Wl[i], Wr[i], Bhp, Blp);
        gather_mean_kernel<<<T / 4, 256>>>(xin, src[i], tlid[i], Ahp, Alp, i > 0);
        dim3 gdim(2, T / 128);
        gemm_mma_kernel<<<gdim, 256>>>(Ahp, Alp, Bhp, Blp, bb[i], hb);
        bn_finalize_kernel<<<256, 128>>>(gam[i], bet[i], T, T / 128);
        xin = hb;
    }
    fc_kernel<<<512, 256>>>(hb, fc_w, fc_b, out);
}

// round 13
// speedup vs baseline: 2.4125x; 1.0262x over previous
#include <cuda_runtime.h>
#include <cuda_bf16.h>
#include <cstdint>

#define EPS 1e-5f

// ---------------- scratch (static device globals; no allocations) ----------------
__device__ __nv_bfloat16 g_Ah[61952 * 512];   // [T, 512] = [agg | tgt], bf16 hi
__device__ __nv_bfloat16 g_Al[61952 * 512];   // bf16 lo residual
__device__ __nv_bfloat16 g_Bh[256 * 512];     // W^T stacked [N=256, K=512], hi
__device__ __nv_bfloat16 g_Bl[256 * 512];     // lo
__device__ float g_h[61952 * 256];
__device__ float g_psum[484 * 256];
__device__ float g_psumsq[484 * 256];
__device__ float g_scale[256];
__device__ float g_shift[256];

// ---------------- helpers ----------------
__device__ __forceinline__ uint32_t smem_u32(const void* p) {
    uint32_t a;
    asm("{ .reg .u64 t; cvta.to.shared.u64 t, %1; cvt.u32.u64 %0, t; }" : "=r"(a) : "l"(p));
    return a;
}
__device__ __forceinline__ void ldsm4(uint32_t& r0, uint32_t& r1, uint32_t& r2, uint32_t& r3,
                                      uint32_t addr) {
    asm volatile("ldmatrix.sync.aligned.m8n8.x4.shared.b16 {%0,%1,%2,%3}, [%4];"
                 : "=r"(r0), "=r"(r1), "=r"(r2), "=r"(r3) : "r"(addr));
}
__device__ __forceinline__ void mma_bf16(float* d, const uint32_t* a, uint32_t b0, uint32_t b1) {
    asm volatile(
        "mma.sync.aligned.m16n8k16.row.col.f32.bf16.bf16.f32 "
        "{%0,%1,%2,%3}, {%4,%5,%6,%7}, {%8,%9}, {%0,%1,%2,%3};"
        : "+f"(d[0]), "+f"(d[1]), "+f"(d[2]), "+f"(d[3])
        : "r"(a[0]), "r"(a[1]), "r"(a[2]), "r"(a[3]), "r"(b0), "r"(b1));
}
__device__ __forceinline__ void cp16(uint32_t saddr, const void* g) {
    asm volatile("cp.async.ca.shared.global [%0], [%1], 16;" :: "r"(saddr), "l"(g));
}
// swizzle for 32B rows: spread 16B chunks so 8-row ldmatrix fetches are conflict-free
__device__ __forceinline__ uint32_t sw32(uint32_t off) {
    return off ^ ((off >> 3) & 0x10);
}

// ---------------- kernel 1: gather + mean + target gather (+ fused BN-apply of prev layer) --
__device__ __forceinline__ void split_store(__nv_bfloat16* ph, __nv_bfloat16* pl, float4 v) {
    __nv_bfloat16 h0 = __float2bfloat16(v.x), h1 = __float2bfloat16(v.y),
                  h2 = __float2bfloat16(v.z), h3 = __float2bfloat16(v.w);
    __nv_bfloat16 l0 = __float2bfloat16(v.x - __bfloat162float(h0));
    __nv_bfloat16 l1 = __float2bfloat16(v.y - __bfloat162float(h1));
    __nv_bfloat16 l2 = __float2bfloat16(v.z - __bfloat162float(h2));
    __nv_bfloat16 l3 = __float2bfloat16(v.w - __bfloat162float(h3));
    *(ushort4*)ph = make_ushort4(__bfloat16_as_ushort(h0), __bfloat16_as_ushort(h1),
                                 __bfloat16_as_ushort(h2), __bfloat16_as_ushort(h3));
    *(ushort4*)pl = make_ushort4(__bfloat16_as_ushort(l0), __bfloat16_as_ushort(l1),
                                 __bfloat16_as_ushort(l2), __bfloat16_as_ushort(l3));
}

__global__ void gather_mean_kernel(const float* __restrict__ x,
                                   const int* __restrict__ src,
                                   const int* __restrict__ tlid,
                                   __nv_bfloat16* __restrict__ Ah,
                                   __nv_bfloat16* __restrict__ Al,
                                   int affine) {
    const int grp  = threadIdx.x >> 6;
    const int lane = threadIdx.x & 63;
    const int t    = blockIdx.x * 4 + grp;
    const float4* x4 = (const float4*)x;

    float4 sc = make_float4(1.f, 1.f, 1.f, 1.f);
    float4 sh = make_float4(0.f, 0.f, 0.f, 0.f);
    if (affine) {
        sc = ((const float4*)g_scale)[lane];
        sh = ((const float4*)g_shift)[lane];
    }

    int base = t * 10;
    int idx[10];
#pragma unroll
    for (int j = 0; j < 10; j++) idx[j] = src[base + j];

    float4 acc = make_float4(0.f, 0.f, 0.f, 0.f);
#pragma unroll
    for (int j = 0; j < 10; j++) {
        float4 v = x4[(size_t)idx[j] * 64 + lane];
        if (affine) {
            v.x = fmaxf(0.f, v.x * sc.x + sh.x);
            v.y = fmaxf(0.f, v.y * sc.y + sh.y);
            v.z = fmaxf(0.f, v.z * sc.z + sh.z);
            v.w = fmaxf(0.f, v.w * sc.w + sh.w);
        }
        acc.x += v.x; acc.y += v.y; acc.z += v.z; acc.w += v.w;
    }
    acc.x *= 0.1f; acc.y *= 0.1f; acc.z *= 0.1f; acc.w *= 0.1f;

    size_t ob = (size_t)t * 512 + lane * 4;
    split_store(Ah + ob, Al + ob, acc);                   // agg -> K cols [0,256)
    float4 tv = x4[(size_t)tlid[t] * 64 + lane];
    if (affine) {
        tv.x = fmaxf(0.f, tv.x * sc.x + sh.x);
        tv.y = fmaxf(0.f, tv.y * sc.y + sh.y);
        tv.z = fmaxf(0.f, tv.z * sc.z + sh.z);
        tv.w = fmaxf(0.f, tv.w * sc.w + sh.w);
    }
    split_store(Ah + ob + 256, Al + ob + 256, tv);        // tgt -> K cols [256,512)
}

// ---------------- kernel 2: W transpose+split ----------------
__global__ void conv_w_kernel(const float* __restrict__ Wl, const float* __restrict__ Wr,
                              __nv_bfloat16* __restrict__ Bh, __nv_bfloat16* __restrict__ Bl) {
    int idx = blockIdx.x * 256 + threadIdx.x;    // 131072 total
    int n = idx >> 9, k = idx & 511;
    float v = (k < 256) ? Wl[k * 256 + n] : Wr[(k - 256) * 256 + n];
    __nv_bfloat16 h = __float2bfloat16(v);
    Bh[idx] = h;
    Bl[idx] = __float2bfloat16(v - __bfloat162float(h));
}

// ---------------- kernel 3: cp.async double-buffered mma.sync GEMM + fused BN stats --------
// BM=128 BN=128 BK=16 x 32 iters, 2 stages. 256 threads, warp grid 2x4, warp tile 64x32.
// Static smem: 2 stages x (A 8KB + B 8KB) = 32KB + stats.
__global__ void __launch_bounds__(256) gemm_mma_kernel(
    const __nv_bfloat16* __restrict__ Ah, const __nv_bfloat16* __restrict__ Al,
    const __nv_bfloat16* __restrict__ Bh, const __nv_bfloat16* __restrict__ Bl,
    const float* __restrict__ bias, float* __restrict__ H) {
    __shared__ __align__(128) char sA[2][8192];   // per stage: hi [0,4096), lo [4096,8192)
    __shared__ __align__(128) char sB[2][8192];
    __shared__ float sm_s[2][128];
    __shared__ float sm_q[2][128];

    const int tid  = threadIdx.x;
    const int lane = tid & 31;
    const int wid  = tid >> 5;
    const int wm   = wid >> 2;        // 0..1   (64 rows)
    const int wn   = wid & 3;         // 0..3   (32 cols)
    const int row0 = blockIdx.y * 128;
    const int col0 = blockIdx.x * 128;

    float acc[4][4][4];
#pragma unroll
    for (int mt = 0; mt < 4; mt++)
#pragma unroll
        for (int nt = 0; nt < 4; nt++)
#pragma unroll
            for (int r = 0; r < 4; r++) acc[mt][nt][r] = 0.f;

    // cp.async mapping: thread t copies one 16B chunk in each of A_h, A_l, B_h, B_l
    const int crow = tid >> 1;            // 0..127
    const int cch  = tid & 1;             // 16B chunk within 32B row
    const uint32_t csw = sw32(crow * 32 + cch * 16);
    const uint32_t sA0 = smem_u32(sA[0]), sA1 = smem_u32(sA[1]);
    const uint32_t sB0 = smem_u32(sB[0]), sB1 = smem_u32(sB[1]);

    // ldmatrix per-lane address parts
    const int a_r = (lane & 7) + ((lane & 8) ? 8 : 0);
    const int a_k = (lane & 16) ? 8 : 0;
    const int b_r = (lane & 7) + ((lane & 16) ? 8 : 0);
    const int b_k = (lane & 8) ? 8 : 0;
    const uint32_t aoff = sw32((wm * 64 + 0 * 16 + a_r) * 32 + a_k * 2);   // mt=0 base
    const uint32_t boff = sw32((wn * 32 + 0 * 16 + b_r) * 32 + b_k * 2);   // np=0 base
    // note: sw32 only XORs bit4 with bit7; row strides of 512B (mt*16 rows) and
    // 512B (np*16 rows) don't change bits <9 uniformly, so recompute per mt/np below.

    const __nv_bfloat16* pAh = Ah + (size_t)(row0 + crow) * 512 + cch * 8;
    const __nv_bfloat16* pAl = Al + (size_t)(row0 + crow) * 512 + cch * 8;
    const __nv_bfloat16* pBh = Bh + (size_t)(col0 + crow) * 512 + cch * 8;
    const __nv_bfloat16* pBl = Bl + (size_t)(col0 + crow) * 512 + cch * 8;

#define ISSUE_STAGE(kb_, uA_, uB_)                           \
    do {                                                     \
        int ko = (kb_) * 16;                                 \
        cp16((uA_) + csw,        pAh + ko);                  \
        cp16((uA_) + 4096 + csw, pAl + ko);                  \
        cp16((uB_) + csw,        pBh + ko);                  \
        cp16((uB_) + 4096 + csw, pBl + ko);                  \
    } while (0)

    // prologue: prefetch kb=0 into stage 0
    ISSUE_STAGE(0, sA0, sB0);
    asm volatile("cp.async.commit_group;");

#pragma unroll 1
    for (int kb = 0; kb < 32; kb++) {
        const int st = kb & 1;
        const uint32_t uA = st ? sA1 : sA0;
        const uint32_t uB = st ? sB1 : sB0;
        if (kb + 1 < 32) {
            ISSUE_STAGE(kb + 1, st ? sA0 : sA1, st ? sB0 : sB1);
        }
        asm volatile("cp.async.commit_group;");
        asm volatile("cp.async.wait_group 1;");
        __syncthreads();

        uint32_t ah[4][4], al[4][4];
#pragma unroll
        for (int mt = 0; mt < 4; mt++) {
            uint32_t off = sw32((wm * 64 + mt * 16 + a_r) * 32 + a_k * 2);
            ldsm4(ah[mt][0], ah[mt][1], ah[mt][2], ah[mt][3], uA + off);
            ldsm4(al[mt][0], al[mt][1], al[mt][2], al[mt][3], uA + 4096 + off);
        }
        uint32_t bh[2][4], bl[2][4];
#pragma unroll
        for (int np = 0; np < 2; np++) {
            uint32_t off = sw32((wn * 32 + np * 16 + b_r) * 32 + b_k * 2);
            ldsm4(bh[np][0], bh[np][1], bh[np][2], bh[np][3], uB + off);
            ldsm4(bl[np][0], bl[np][1], bl[np][2], bl[np][3], uB + 4096 + off);
        }
#pragma unroll
        for (int mt = 0; mt < 4; mt++)
#pragma unroll
            for (int nt = 0; nt < 4; nt++) {
                uint32_t b0h = bh[nt >> 1][(nt & 1) * 2];
                uint32_t b1h = bh[nt >> 1][(nt & 1) * 2 + 1];
                uint32_t b0l = bl[nt >> 1][(nt & 1) * 2];
                uint32_t b1l = bl[nt >> 1][(nt & 1) * 2 + 1];
                mma_bf16(acc[mt][nt], ah[mt], b0h, b1h);   // Ah*Bh
                mma_bf16(acc[mt][nt], al[mt], b0h, b1h);   // Al*Bh
                mma_bf16(acc[mt][nt], ah[mt], b0l, b1l);   // Ah*Bl
            }
        __syncthreads();
    }
#undef ISSUE_STAGE

    // ---- epilogue: add bias, write H, accumulate per-column stats ----
#pragma unroll
    for (int nt = 0; nt < 4; nt++) {
        int c = col0 + wn * 32 + nt * 8 + (lane & 3) * 2;
        float b0 = bias[c], b1 = bias[c + 1];
        float s0 = 0.f, s1 = 0.f, q0 = 0.f, q1 = 0.f;
#pragma unroll
        for (int mt = 0; mt < 4; mt++) {
            int r0 = row0 + wm * 64 + mt * 16 + (lane >> 2);
            float h0 = acc[mt][nt][0] + b0;
            float h1 = acc[mt][nt][1] + b1;
            float h2 = acc[mt][nt][2] + b0;
            float h3 = acc[mt][nt][3] + b1;
            *(float2*)&H[(size_t)r0 * 256 + c] = make_float2(h0, h1);
            *(float2*)&H[(size_t)(r0 + 8) * 256 + c] = make_float2(h2, h3);
            s0 += h0 + h2;  s1 += h1 + h3;
            q0 += h0 * h0 + h2 * h2;
            q1 += h1 * h1 + h3 * h3;
        }
#pragma unroll
        for (int off = 4; off < 32; off <<= 1) {
            s0 += __shfl_xor_sync(0xFFFFFFFFu, s0, off);
            s1 += __shfl_xor_sync(0xFFFFFFFFu, s1, off);
            q0 += __shfl_xor_sync(0xFFFFFFFFu, q0, off);
            q1 += __shfl_xor_sync(0xFFFFFFFFu, q1, off);
        }
        if (lane < 4) {
            int cl = wn * 32 + nt * 8 + lane * 2;
            sm_s[wm][cl] = s0;  sm_s[wm][cl + 1] = s1;
            sm_q[wm][cl] = q0;  sm_q[wm][cl + 1] = q1;
        }
    }
    __syncthreads();
    if (tid < 128) {
        g_psum[blockIdx.y * 256 + col0 + tid]   = sm_s[0][tid] + sm_s[1][tid];
        g_psumsq[blockIdx.y * 256 + col0 + tid] = sm_q[0][tid] + sm_q[1][tid];
    }
}

// ---------------- kernel 4: finalize BN affine (one block per column) ----------------
__global__ void bn_finalize_kernel(const float* __restrict__ gam,
                                   const float* __restrict__ beta,
                                   int M, int NB) {
    const int col = blockIdx.x;
    const int t = threadIdx.x;
    float s = 0.f, ss = 0.f;
    for (int i = t; i < NB; i += 128) {
        s  += g_psum[i * 256 + col];
        ss += g_psumsq[i * 256 + col];
    }
    __shared__ float shs[128], shq[128];
    shs[t] = s; shq[t] = ss;
    __syncthreads();
    for (int o = 64; o > 0; o >>= 1) {
        if (t < o) { shs[t] += shs[t + o]; shq[t] += shq[t + o]; }
        __syncthreads();
    }
    if (t == 0) {
        float inv_m = 1.f / (float)M;
        float mu  = shs[0] * inv_m;
        float var = shq[0] * inv_m - mu * mu;
        float inv = rsqrtf(var + EPS);
        float sc  = gam[col] * inv;
        g_scale[col] = sc;
        g_shift[col] = beta[col] - mu * sc;
    }
}

// ---------------- kernel 5: out = relu(bn(H3)) @ fc_w + fc_b  ([512,256]@[256,47]) ---------
__global__ void fc_kernel(const float* __restrict__ Hx, const float* __restrict__ W,
                          const float* __restrict__ b, float* __restrict__ out) {
    __shared__ float xs[256];
    const int row = blockIdx.x;
    const int t = threadIdx.x;
    xs[t] = fmaxf(0.f, Hx[row * 256 + t] * g_scale[t] + g_shift[t]);
    __syncthreads();
    if (t < 47) {
        float acc = b[t];
#pragma unroll 8
        for (int k = 0; k < 256; k++) acc += xs[k] * W[k * 47 + t];
        out[row * 47 + t] = acc;
    }
}

// ---------------- host ----------------
extern "C" void kernel_launch(void* const* d_in, const int* in_sizes, int n_in,
                              void* d_out, int out_size) {
    const bool dict_order = (in_sizes[4] == 65536);

    const float* x_feat = (const float*)d_in[0];
    const int *src[3], *tlid[3];
    const float *Wl[3], *Wr[3], *bb[3], *gam[3], *bet[3];
    if (dict_order) {
        for (int i = 0; i < 3; i++) {
            int base = 1 + i * 8;
            src[i]  = (const int*)d_in[base + 0];
            tlid[i] = (const int*)d_in[base + 2];
            Wl[i]   = (const float*)d_in[base + 3];
            Wr[i]   = (const float*)d_in[base + 4];
            bb[i]   = (const float*)d_in[base + 5];
            gam[i]  = (const float*)d_in[base + 6];
            bet[i]  = (const float*)d_in[base + 7];
        }
    } else {
        for (int i = 0; i < 3; i++) {
            src[i]  = (const int*)d_in[1 + i * 3];
            tlid[i] = (const int*)d_in[3 + i * 3];
            Wl[i]   = (const float*)d_in[10 + i * 5];
            Wr[i]   = (const float*)d_in[11 + i * 5];
            bb[i]   = (const float*)d_in[12 + i * 5];
            gam[i]  = (const float*)d_in[13 + i * 5];
            bet[i]  = (const float*)d_in[14 + i * 5];
        }
    }
    const float* fc_w = (const float*)d_in[25];
    const float* fc_b = (const float*)d_in[26];
    float* out = (float*)d_out;

    __nv_bfloat16 *Ahp, *Alp, *Bhp, *Blp;
    float *hb;
    cudaGetSymbolAddress((void**)&Ahp, g_Ah);
    cudaGetSymbolAddress((void**)&Alp, g_Al);
    cudaGetSymbolAddress((void**)&Bhp, g_Bh);
    cudaGetSymbolAddress((void**)&Blp, g_Bl);
    cudaGetSymbolAddress((void**)&hb,  g_h);

    const int NT[3] = {61952, 5632, 512};
    const float* xin = x_feat;

    for (int i = 0; i < 3; i++) {
        const int T = NT[i];
        conv_w_kernel<<<512, 256>>>(Wl[i], Wr[i], Bhp, Blp);
        gather_mean_kernel<<<T / 4, 256>>>(xin, src[i], tlid[i], Ahp, Alp, i > 0);
        dim3 gdim(2, T / 128);
        gemm_mma_kernel<<<gdim, 256>>>(Ahp, Alp, Bhp, Blp, bb[i], hb);
        bn_finalize_kernel<<<256, 128>>>(gam[i], bet[i], T, T / 128);
        xin = hb;
    }
    fc_kernel<<<512, 256>>>(hb, fc_w, fc_b, out);
}

// round 14
// speedup vs baseline: 2.4293x; 1.0069x over previous
#include <cuda_runtime.h>
#include <cuda_bf16.h>
#include <cstdint>

#define EPS 1e-5f

// ---------------- scratch (static device globals; no allocations) ----------------
__device__ __nv_bfloat16 g_Ah[61952 * 512];     // [T, 512] = [agg | tgt], bf16 hi
__device__ __nv_bfloat16 g_Al[61952 * 512];     // bf16 lo residual
__device__ __nv_bfloat16 g_Bh[3 * 256 * 512];   // per-layer W^T stacked [N=256, K=512], hi
__device__ __nv_bfloat16 g_Bl[3 * 256 * 512];   // lo
__device__ float g_h[61952 * 256];
__device__ float g_psum[256 * 484];             // TRANSPOSED: [col][block]
__device__ float g_psumsq[256 * 484];
__device__ float g_scale[256];
__device__ float g_shift[256];

// ---------------- helpers ----------------
__device__ __forceinline__ uint32_t smem_u32(const void* p) {
    uint32_t a;
    asm("{ .reg .u64 t; cvta.to.shared.u64 t, %1; cvt.u32.u64 %0, t; }" : "=r"(a) : "l"(p));
    return a;
}
__device__ __forceinline__ void ldsm4(uint32_t& r0, uint32_t& r1, uint32_t& r2, uint32_t& r3,
                                      uint32_t addr) {
    asm volatile("ldmatrix.sync.aligned.m8n8.x4.shared.b16 {%0,%1,%2,%3}, [%4];"
                 : "=r"(r0), "=r"(r1), "=r"(r2), "=r"(r3) : "r"(addr));
}
__device__ __forceinline__ void mma_bf16(float* d, const uint32_t* a, uint32_t b0, uint32_t b1) {
    asm volatile(
        "mma.sync.aligned.m16n8k16.row.col.f32.bf16.bf16.f32 "
        "{%0,%1,%2,%3}, {%4,%5,%6,%7}, {%8,%9}, {%0,%1,%2,%3};"
        : "+f"(d[0]), "+f"(d[1]), "+f"(d[2]), "+f"(d[3])
        : "r"(a[0]), "r"(a[1]), "r"(a[2]), "r"(a[3]), "r"(b0), "r"(b1));
}
__device__ __forceinline__ void cp16(uint32_t saddr, const void* g) {
    asm volatile("cp.async.ca.shared.global [%0], [%1], 16;" :: "r"(saddr), "l"(g));
}
// swizzle for 32B rows
__device__ __forceinline__ uint32_t sw32(uint32_t off) {
    return off ^ ((off >> 3) & 0x10);
}

// ---------------- kernel 1: gather + mean + target gather (+ fused BN-apply of prev layer) --
__device__ __forceinline__ void split_store(__nv_bfloat16* ph, __nv_bfloat16* pl, float4 v) {
    __nv_bfloat16 h0 = __float2bfloat16(v.x), h1 = __float2bfloat16(v.y),
                  h2 = __float2bfloat16(v.z), h3 = __float2bfloat16(v.w);
    __nv_bfloat16 l0 = __float2bfloat16(v.x - __bfloat162float(h0));
    __nv_bfloat16 l1 = __float2bfloat16(v.y - __bfloat162float(h1));
    __nv_bfloat16 l2 = __float2bfloat16(v.z - __bfloat162float(h2));
    __nv_bfloat16 l3 = __float2bfloat16(v.w - __bfloat162float(h3));
    *(ushort4*)ph = make_ushort4(__bfloat16_as_ushort(h0), __bfloat16_as_ushort(h1),
                                 __bfloat16_as_ushort(h2), __bfloat16_as_ushort(h3));
    *(ushort4*)pl = make_ushort4(__bfloat16_as_ushort(l0), __bfloat16_as_ushort(l1),
                                 __bfloat16_as_ushort(l2), __bfloat16_as_ushort(l3));
}

__global__ void gather_mean_kernel(const float* __restrict__ x,
                                   const int* __restrict__ src,
                                   const int* __restrict__ tlid,
                                   __nv_bfloat16* __restrict__ Ah,
                                   __nv_bfloat16* __restrict__ Al,
                                   int affine) {
    const int grp  = threadIdx.x >> 6;
    const int lane = threadIdx.x & 63;
    const int t    = blockIdx.x * 4 + grp;
    const float4* x4 = (const float4*)x;

    float4 sc = make_float4(1.f, 1.f, 1.f, 1.f);
    float4 sh = make_float4(0.f, 0.f, 0.f, 0.f);
    if (affine) {
        sc = ((const float4*)g_scale)[lane];
        sh = ((const float4*)g_shift)[lane];
    }

    int base = t * 10;
    int idx[10];
#pragma unroll
    for (int j = 0; j < 10; j++) idx[j] = src[base + j];

    float4 acc = make_float4(0.f, 0.f, 0.f, 0.f);
#pragma unroll
    for (int j = 0; j < 10; j++) {
        float4 v = x4[(size_t)idx[j] * 64 + lane];
        if (affine) {
            v.x = fmaxf(0.f, v.x * sc.x + sh.x);
            v.y = fmaxf(0.f, v.y * sc.y + sh.y);
            v.z = fmaxf(0.f, v.z * sc.z + sh.z);
            v.w = fmaxf(0.f, v.w * sc.w + sh.w);
        }
        acc.x += v.x; acc.y += v.y; acc.z += v.z; acc.w += v.w;
    }
    acc.x *= 0.1f; acc.y *= 0.1f; acc.z *= 0.1f; acc.w *= 0.1f;

    size_t ob = (size_t)t * 512 + lane * 4;
    split_store(Ah + ob, Al + ob, acc);                   // agg -> K cols [0,256)
    float4 tv = x4[(size_t)tlid[t] * 64 + lane];
    if (affine) {
        tv.x = fmaxf(0.f, tv.x * sc.x + sh.x);
        tv.y = fmaxf(0.f, tv.y * sc.y + sh.y);
        tv.z = fmaxf(0.f, tv.z * sc.z + sh.z);
        tv.w = fmaxf(0.f, tv.w * sc.w + sh.w);
    }
    split_store(Ah + ob + 256, Al + ob + 256, tv);        // tgt -> K cols [256,512)
}

// ---------------- kernel 2: W transpose+split ----------------
__global__ void conv_w_kernel(const float* __restrict__ Wl, const float* __restrict__ Wr,
                              __nv_bfloat16* __restrict__ Bh, __nv_bfloat16* __restrict__ Bl) {
    int idx = blockIdx.x * 256 + threadIdx.x;    // 131072 total
    int n = idx >> 9, k = idx & 511;
    float v = (k < 256) ? Wl[k * 256 + n] : Wr[(k - 256) * 256 + n];
    __nv_bfloat16 h = __float2bfloat16(v);
    Bh[idx] = h;
    Bl[idx] = __float2bfloat16(v - __bfloat162float(h));
}

// ---------------- kernel 3: cp.async double-buffered mma.sync GEMM + fused BN stats --------
// BM=128 BN=128 BK=16 x 32 iters, 2 stages. 256 threads, warp grid 2x4, warp tile 64x32.
// A-fragments loaded in mt-halves to keep regs <=128 -> 2 CTAs/SM.
__global__ void __launch_bounds__(256, 2) gemm_mma_kernel(
    const __nv_bfloat16* __restrict__ Ah, const __nv_bfloat16* __restrict__ Al,
    const __nv_bfloat16* __restrict__ Bh, const __nv_bfloat16* __restrict__ Bl,
    const float* __restrict__ bias, float* __restrict__ H) {
    __shared__ __align__(128) char sA[2][8192];   // per stage: hi [0,4096), lo [4096,8192)
    __shared__ __align__(128) char sB[2][8192];
    __shared__ float sm_s[2][128];
    __shared__ float sm_q[2][128];

    const int tid  = threadIdx.x;
    const int lane = tid & 31;
    const int wid  = tid >> 5;
    const int wm   = wid >> 2;        // 0..1   (64 rows)
    const int wn   = wid & 3;         // 0..3   (32 cols)
    const int row0 = blockIdx.y * 128;
    const int col0 = blockIdx.x * 128;

    float acc[4][4][4];
#pragma unroll
    for (int mt = 0; mt < 4; mt++)
#pragma unroll
        for (int nt = 0; nt < 4; nt++)
#pragma unroll
            for (int r = 0; r < 4; r++) acc[mt][nt][r] = 0.f;

    const int crow = tid >> 1;            // 0..127
    const int cch  = tid & 1;             // 16B chunk within 32B row
    const uint32_t csw = sw32(crow * 32 + cch * 16);
    const uint32_t sA0 = smem_u32(sA[0]), sA1 = smem_u32(sA[1]);
    const uint32_t sB0 = smem_u32(sB[0]), sB1 = smem_u32(sB[1]);

    const int a_r = (lane & 7) + ((lane & 8) ? 8 : 0);
    const int a_k = (lane & 16) ? 8 : 0;
    const int b_r = (lane & 7) + ((lane & 16) ? 8 : 0);
    const int b_k = (lane & 8) ? 8 : 0;

    const __nv_bfloat16* pAh = Ah + (size_t)(row0 + crow) * 512 + cch * 8;
    const __nv_bfloat16* pAl = Al + (size_t)(row0 + crow) * 512 + cch * 8;
    const __nv_bfloat16* pBh = Bh + (size_t)(col0 + crow) * 512 + cch * 8;
    const __nv_bfloat16* pBl = Bl + (size_t)(col0 + crow) * 512 + cch * 8;

#define ISSUE_STAGE(kb_, uA_, uB_)                           \
    do {                                                     \
        int ko = (kb_) * 16;                                 \
        cp16((uA_) + csw,        pAh + ko);                  \
        cp16((uA_) + 4096 + csw, pAl + ko);                  \
        cp16((uB_) + csw,        pBh + ko);                  \
        cp16((uB_) + 4096 + csw, pBl + ko);                  \
    } while (0)

    ISSUE_STAGE(0, sA0, sB0);
    asm volatile("cp.async.commit_group;");

#pragma unroll 1
    for (int kb = 0; kb < 32; kb++) {
        const int st = kb & 1;
        const uint32_t uA = st ? sA1 : sA0;
        const uint32_t uB = st ? sB1 : sB0;
        if (kb + 1 < 32) {
            ISSUE_STAGE(kb + 1, st ? sA0 : sA1, st ? sB0 : sB1);
        }
        asm volatile("cp.async.commit_group;");
        asm volatile("cp.async.wait_group 1;");
        __syncthreads();

        uint32_t bh[2][4], bl[2][4];
#pragma unroll
        for (int np = 0; np < 2; np++) {
            uint32_t off = sw32((wn * 32 + np * 16 + b_r) * 32 + b_k * 2);
            ldsm4(bh[np][0], bh[np][1], bh[np][2], bh[np][3], uB + off);
            ldsm4(bl[np][0], bl[np][1], bl[np][2], bl[np][3], uB + 4096 + off);
        }
        // process A in mt-halves to cap register pressure (2 CTAs/SM)
#pragma unroll
        for (int mh = 0; mh < 2; mh++) {
            uint32_t ah[2][4], al[2][4];
#pragma unroll
            for (int mi = 0; mi < 2; mi++) {
                int mt = mh * 2 + mi;
                uint32_t off = sw32((wm * 64 + mt * 16 + a_r) * 32 + a_k * 2);
                ldsm4(ah[mi][0], ah[mi][1], ah[mi][2], ah[mi][3], uA + off);
                ldsm4(al[mi][0], al[mi][1], al[mi][2], al[mi][3], uA + 4096 + off);
            }
#pragma unroll
            for (int mi = 0; mi < 2; mi++)
#pragma unroll
                for (int nt = 0; nt < 4; nt++) {
                    uint32_t b0h = bh[nt >> 1][(nt & 1) * 2];
                    uint32_t b1h = bh[nt >> 1][(nt & 1) * 2 + 1];
                    uint32_t b0l = bl[nt >> 1][(nt & 1) * 2];
                    uint32_t b1l = bl[nt >> 1][(nt & 1) * 2 + 1];
                    float* a4 = acc[mh * 2 + mi][nt];
                    mma_bf16(a4, ah[mi], b0h, b1h);   // Ah*Bh
                    mma_bf16(a4, al[mi], b0h, b1h);   // Al*Bh
                    mma_bf16(a4, ah[mi], b0l, b1l);   // Ah*Bl
                }
        }
        __syncthreads();
    }
#undef ISSUE_STAGE

    // ---- epilogue: add bias, write H, accumulate per-column stats ----
#pragma unroll
    for (int nt = 0; nt < 4; nt++) {
        int c = col0 + wn * 32 + nt * 8 + (lane & 3) * 2;
        float b0 = bias[c], b1 = bias[c + 1];
        float s0 = 0.f, s1 = 0.f, q0 = 0.f, q1 = 0.f;
#pragma unroll
        for (int mt = 0; mt < 4; mt++) {
            int r0 = row0 + wm * 64 + mt * 16 + (lane >> 2);
            float h0 = acc[mt][nt][0] + b0;
            float h1 = acc[mt][nt][1] + b1;
            float h2 = acc[mt][nt][2] + b0;
            float h3 = acc[mt][nt][3] + b1;
            *(float2*)&H[(size_t)r0 * 256 + c] = make_float2(h0, h1);
            *(float2*)&H[(size_t)(r0 + 8) * 256 + c] = make_float2(h2, h3);
            s0 += h0 + h2;  s1 += h1 + h3;
            q0 += h0 * h0 + h2 * h2;
            q1 += h1 * h1 + h3 * h3;
        }
#pragma unroll
        for (int off = 4; off < 32; off <<= 1) {
            s0 += __shfl_xor_sync(0xFFFFFFFFu, s0, off);
            s1 += __shfl_xor_sync(0xFFFFFFFFu, s1, off);
            q0 += __shfl_xor_sync(0xFFFFFFFFu, q0, off);
            q1 += __shfl_xor_sync(0xFFFFFFFFu, q1, off);
        }
        if (lane < 4) {
            int cl = wn * 32 + nt * 8 + lane * 2;
            sm_s[wm][cl] = s0;  sm_s[wm][cl + 1] = s1;
            sm_q[wm][cl] = q0;  sm_q[wm][cl + 1] = q1;
        }
    }
    __syncthreads();
    if (tid < 128) {
        // transposed layout: [col][block] for coalesced finalize reads
        g_psum[(col0 + tid) * 484 + blockIdx.y]   = sm_s[0][tid] + sm_s[1][tid];
        g_psumsq[(col0 + tid) * 484 + blockIdx.y] = sm_q[0][tid] + sm_q[1][tid];
    }
}

// ---------------- kernel 4: finalize BN affine (one block per column, coalesced) -----------
__global__ void bn_finalize_kernel(const float* __restrict__ gam,
                                   const float* __restrict__ beta,
                                   int M, int NB) {
    const int col = blockIdx.x;
    const int t = threadIdx.x;
    float s = 0.f, ss = 0.f;
    for (int i = t; i < NB; i += 128) {
        s  += g_psum[col * 484 + i];
        ss += g_psumsq[col * 484 + i];
    }
    __shared__ float shs[128], shq[128];
    shs[t] = s; shq[t] = ss;
    __syncthreads();
    for (int o = 64; o > 0; o >>= 1) {
        if (t < o) { shs[t] += shs[t + o]; shq[t] += shq[t + o]; }
        __syncthreads();
    }
    if (t == 0) {
        float inv_m = 1.f / (float)M;
        float mu  = shs[0] * inv_m;
        float var = shq[0] * inv_m - mu * mu;
        float inv = rsqrtf(var + EPS);
        float sc  = gam[col] * inv;
        g_scale[col] = sc;
        g_shift[col] = beta[col] - mu * sc;
    }
}

// ---------------- kernel 5: out = relu(bn(H3)) @ fc_w + fc_b  ([512,256]@[256,47]) ---------
__global__ void fc_kernel(const float* __restrict__ Hx, const float* __restrict__ W,
                          const float* __restrict__ b, float* __restrict__ out) {
    __shared__ float xs[256];
    const int row = blockIdx.x;
    const int t = threadIdx.x;
    xs[t] = fmaxf(0.f, Hx[row * 256 + t] * g_scale[t] + g_shift[t]);
    __syncthreads();
    if (t < 47) {
        float acc = b[t];
#pragma unroll 8
        for (int k = 0; k < 256; k++) acc += xs[k] * W[k * 47 + t];
        out[row * 47 + t] = acc;
    }
}

// ---------------- host ----------------
extern "C" void kernel_launch(void* const* d_in, const int* in_sizes, int n_in,
                              void* d_out, int out_size) {
    const bool dict_order = (in_sizes[4] == 65536);

    const float* x_feat = (const float*)d_in[0];
    const int *src[3], *tlid[3];
    const float *Wl[3], *Wr[3], *bb[3], *gam[3], *bet[3];
    if (dict_order) {
        for (int i = 0; i < 3; i++) {
            int base = 1 + i * 8;
            src[i]  = (const int*)d_in[base + 0];
            tlid[i] = (const int*)d_in[base + 2];
            Wl[i]   = (const float*)d_in[base + 3];
            Wr[i]   = (const float*)d_in[base + 4];
            bb[i]   = (const float*)d_in[base + 5];
            gam[i]  = (const float*)d_in[base + 6];
            bet[i]  = (const float*)d_in[base + 7];
        }
    } else {
        for (int i = 0; i < 3; i++) {
            src[i]  = (const int*)d_in[1 + i * 3];
            tlid[i] = (const int*)d_in[3 + i * 3];
            Wl[i]   = (const float*)d_in[10 + i * 5];
            Wr[i]   = (const float*)d_in[11 + i * 5];
            bb[i]   = (const float*)d_in[12 + i * 5];
            gam[i]  = (const float*)d_in[13 + i * 5];
            bet[i]  = (const float*)d_in[14 + i * 5];
        }
    }
    const float* fc_w = (const float*)d_in[25];
    const float* fc_b = (const float*)d_in[26];
    float* out = (float*)d_out;

    __nv_bfloat16 *Ahp, *Alp, *Bhp, *Blp;
    float *hb;
    cudaGetSymbolAddress((void**)&Ahp, g_Ah);
    cudaGetSymbolAddress((void**)&Alp, g_Al);
    cudaGetSymbolAddress((void**)&Bhp, g_Bh);
    cudaGetSymbolAddress((void**)&Blp, g_Bl);
    cudaGetSymbolAddress((void**)&hb,  g_h);

    const int NT[3] = {61952, 5632, 512};
    const float* xin = x_feat;

    // all weight conversions upfront (off the critical dependency chain)
    for (int i = 0; i < 3; i++)
        conv_w_kernel<<<512, 256>>>(Wl[i], Wr[i], Bhp + i * 131072, Blp + i * 131072);

    for (int i = 0; i < 3; i++) {
        const int T = NT[i];
        gather_mean_kernel<<<T / 4, 256>>>(xin, src[i], tlid[i], Ahp, Alp, i > 0);
        dim3 gdim(2, T / 128);
        gemm_mma_kernel<<<gdim, 256>>>(Ahp, Alp, Bhp + i * 131072, Blp + i * 131072,
                                       bb[i], hb);
        bn_finalize_kernel<<<256, 128>>>(gam[i], bet[i], T, T / 128);
        xin = hb;
    }
    fc_kernel<<<512, 256>>>(hb, fc_w, fc_b, out);
}

// round 16
// speedup vs baseline: 2.4422x; 1.0053x over previous
#include <cuda_runtime.h>
#include <cuda_bf16.h>
#include <cstdint>

#define EPS 1e-5f

// ---------------- scratch (static device globals; no allocations) ----------------
__device__ __nv_bfloat16 g_Ah[61952 * 512];     // [T, 512] = [agg | tgt], bf16 hi
__device__ __nv_bfloat16 g_Al[61952 * 512];     // bf16 lo residual
__device__ __nv_bfloat16 g_Bh[3 * 256 * 512];   // per-layer W^T stacked [N=256, K=512], hi
__device__ __nv_bfloat16 g_Bl[3 * 256 * 512];   // lo
__device__ float g_h[61952 * 256];
__device__ float g_psum[256 * 484];             // [col][block]
__device__ float g_psumsq[256 * 484];
__device__ float g_scale[256];
__device__ float g_shift[256];

// ---------------- helpers ----------------
__device__ __forceinline__ uint32_t smem_u32(const void* p) {
    uint32_t a;
    asm("{ .reg .u64 t; cvta.to.shared.u64 t, %1; cvt.u32.u64 %0, t; }" : "=r"(a) : "l"(p));
    return a;
}
__device__ __forceinline__ void ldsm4(uint32_t& r0, uint32_t& r1, uint32_t& r2, uint32_t& r3,
                                      uint32_t addr) {
    asm volatile("ldmatrix.sync.aligned.m8n8.x4.shared.b16 {%0,%1,%2,%3}, [%4];"
                 : "=r"(r0), "=r"(r1), "=r"(r2), "=r"(r3) : "r"(addr));
}
__device__ __forceinline__ void mma_bf16(float* d, const uint32_t* a, uint32_t b0, uint32_t b1) {
    asm volatile(
        "mma.sync.aligned.m16n8k16.row.col.f32.bf16.bf16.f32 "
        "{%0,%1,%2,%3}, {%4,%5,%6,%7}, {%8,%9}, {%0,%1,%2,%3};"
        : "+f"(d[0]), "+f"(d[1]), "+f"(d[2]), "+f"(d[3])
        : "r"(a[0]), "r"(a[1]), "r"(a[2]), "r"(a[3]), "r"(b0), "r"(b1));
}
__device__ __forceinline__ void cp16(uint32_t saddr, const void* g) {
    asm volatile("cp.async.ca.shared.global [%0], [%1], 16;" :: "r"(saddr), "l"(g));
}
// swizzle for 32B rows
__device__ __forceinline__ uint32_t sw32(uint32_t off) {
    return off ^ ((off >> 3) & 0x10);
}

// ---------------- kernel 1: gather + mean + target gather (+ fused BN-apply of prev layer) --
__device__ __forceinline__ void split_store(__nv_bfloat16* ph, __nv_bfloat16* pl, float4 v) {
    __nv_bfloat16 h0 = __float2bfloat16(v.x), h1 = __float2bfloat16(v.y),
                  h2 = __float2bfloat16(v.z), h3 = __float2bfloat16(v.w);
    __nv_bfloat16 l0 = __float2bfloat16(v.x - __bfloat162float(h0));
    __nv_bfloat16 l1 = __float2bfloat16(v.y - __bfloat162float(h1));
    __nv_bfloat16 l2 = __float2bfloat16(v.z - __bfloat162float(h2));
    __nv_bfloat16 l3 = __float2bfloat16(v.w - __bfloat162float(h3));
    *(ushort4*)ph = make_ushort4(__bfloat16_as_ushort(h0), __bfloat16_as_ushort(h1),
                                 __bfloat16_as_ushort(h2), __bfloat16_as_ushort(h3));
    *(ushort4*)pl = make_ushort4(__bfloat16_as_ushort(l0), __bfloat16_as_ushort(l1),
                                 __bfloat16_as_ushort(l2), __bfloat16_as_ushort(l3));
}

__global__ void gather_mean_kernel(const float* __restrict__ x,
                                   const int* __restrict__ src,
                                   const int* __restrict__ tlid,
                                   __nv_bfloat16* __restrict__ Ah,
                                   __nv_bfloat16* __restrict__ Al,
                                   int affine) {
    const int grp  = threadIdx.x >> 6;
    const int lane = threadIdx.x & 63;
    const int t    = blockIdx.x * 4 + grp;
    const float4* x4 = (const float4*)x;

    float4 sc = make_float4(1.f, 1.f, 1.f, 1.f);
    float4 sh = make_float4(0.f, 0.f, 0.f, 0.f);
    if (affine) {
        sc = ((const float4*)g_scale)[lane];
        sh = ((const float4*)g_shift)[lane];
    }

    int base = t * 10;
    int idx[10];
#pragma unroll
    for (int j = 0; j < 10; j++) idx[j] = src[base + j];

    float4 acc = make_float4(0.f, 0.f, 0.f, 0.f);
#pragma unroll
    for (int j = 0; j < 10; j++) {
        float4 v = x4[(size_t)idx[j] * 64 + lane];
        if (affine) {
            v.x = fmaxf(0.f, v.x * sc.x + sh.x);
            v.y = fmaxf(0.f, v.y * sc.y + sh.y);
            v.z = fmaxf(0.f, v.z * sc.z + sh.z);
            v.w = fmaxf(0.f, v.w * sc.w + sh.w);
        }
        acc.x += v.x; acc.y += v.y; acc.z += v.z; acc.w += v.w;
    }
    acc.x *= 0.1f; acc.y *= 0.1f; acc.z *= 0.1f; acc.w *= 0.1f;

    size_t ob = (size_t)t * 512 + lane * 4;
    split_store(Ah + ob, Al + ob, acc);                   // agg -> K cols [0,256)
    float4 tv = x4[(size_t)tlid[t] * 64 + lane];
    if (affine) {
        tv.x = fmaxf(0.f, tv.x * sc.x + sh.x);
        tv.y = fmaxf(0.f, tv.y * sc.y + sh.y);
        tv.z = fmaxf(0.f, tv.z * sc.z + sh.z);
        tv.w = fmaxf(0.f, tv.w * sc.w + sh.w);
    }
    split_store(Ah + ob + 256, Al + ob + 256, tv);        // tgt -> K cols [256,512)
}

// ---------------- kernel 2: W transpose+split ----------------
__global__ void conv_w_kernel(const float* __restrict__ Wl, const float* __restrict__ Wr,
                              __nv_bfloat16* __restrict__ Bh, __nv_bfloat16* __restrict__ Bl) {
    int idx = blockIdx.x * 256 + threadIdx.x;    // 131072 total
    int n = idx >> 9, k = idx & 511;
    float v = (k < 256) ? Wl[k * 256 + n] : Wr[(k - 256) * 256 + n];
    __nv_bfloat16 h = __float2bfloat16(v);
    Bh[idx] = h;
    Bl[idx] = __float2bfloat16(v - __bfloat162float(h));
}

// ---------------- kernel 3: cp.async double-buffered mma.sync GEMM + fused BN stats --------
// BM=128 BN=128 BK=16 x 32 iters, 2 stages, ONE barrier per K-iter.
__global__ void __launch_bounds__(256, 2) gemm_mma_kernel(
    const __nv_bfloat16* __restrict__ Ah, const __nv_bfloat16* __restrict__ Al,
    const __nv_bfloat16* __restrict__ Bh, const __nv_bfloat16* __restrict__ Bl,
    const float* __restrict__ bias, float* __restrict__ H) {
    __shared__ __align__(128) char sA[2][8192];   // per stage: hi [0,4096), lo [4096,8192)
    __shared__ __align__(128) char sB[2][8192];
    __shared__ float sm_s[2][128];
    __shared__ float sm_q[2][128];

    const int tid  = threadIdx.x;
    const int lane = tid & 31;
    const int wid  = tid >> 5;
    const int wm   = wid >> 2;        // 0..1   (64 rows)
    const int wn   = wid & 3;         // 0..3   (32 cols)
    const int row0 = blockIdx.y * 128;
    const int col0 = blockIdx.x * 128;

    float acc[4][4][4];
#pragma unroll
    for (int mt = 0; mt < 4; mt++)
#pragma unroll
        for (int nt = 0; nt < 4; nt++)
#pragma unroll
            for (int r = 0; r < 4; r++) acc[mt][nt][r] = 0.f;

    const int crow = tid >> 1;            // 0..127
    const int cch  = tid & 1;             // 16B chunk within 32B row
    const uint32_t csw = sw32(crow * 32 + cch * 16);
    const uint32_t sA0 = smem_u32(sA[0]), sA1 = smem_u32(sA[1]);
    const uint32_t sB0 = smem_u32(sB[0]), sB1 = smem_u32(sB[1]);

    const int a_r = (lane & 7) + ((lane & 8) ? 8 : 0);
    const int a_k = (lane & 16) ? 8 : 0;
    const int b_r = (lane & 7) + ((lane & 16) ? 8 : 0);
    const int b_k = (lane & 8) ? 8 : 0;

    const __nv_bfloat16* pAh = Ah + (size_t)(row0 + crow) * 512 + cch * 8;
    const __nv_bfloat16* pAl = Al + (size_t)(row0 + crow) * 512 + cch * 8;
    const __nv_bfloat16* pBh = Bh + (size_t)(col0 + crow) * 512 + cch * 8;
    const __nv_bfloat16* pBl = Bl + (size_t)(col0 + crow) * 512 + cch * 8;

#define ISSUE_STAGE(kb_, uA_, uB_)                           \
    do {                                                     \
        int ko = (kb_) * 16;                                 \
        cp16((uA_) + csw,        pAh + ko);                  \
        cp16((uA_) + 4096 + csw, pAl + ko);                  \
        cp16((uB_) + csw,        pBh + ko);                  \
        cp16((uB_) + 4096 + csw, pBl + ko);                  \
    } while (0)

    ISSUE_STAGE(0, sA0, sB0);
    asm volatile("cp.async.commit_group;");

#pragma unroll 1
    for (int kb = 0; kb < 32; kb++) {
        const int st = kb & 1;
        const uint32_t uA = st ? sA1 : sA0;
        const uint32_t uB = st ? sB1 : sB0;

        // group kb arrived (everywhere) + all threads done with buffer st^1
        asm volatile("cp.async.wait_group 0;");
        __syncthreads();
        if (kb + 1 < 32) {
            ISSUE_STAGE(kb + 1, st ? sA0 : sA1, st ? sB0 : sB1);
            asm volatile("cp.async.commit_group;");
        }

        uint32_t bh[2][4], bl[2][4];
#pragma unroll
        for (int np = 0; np < 2; np++) {
            uint32_t off = sw32((wn * 32 + np * 16 + b_r) * 32 + b_k * 2);
            ldsm4(bh[np][0], bh[np][1], bh[np][2], bh[np][3], uB + off);
            ldsm4(bl[np][0], bl[np][1], bl[np][2], bl[np][3], uB + 4096 + off);
        }
#pragma unroll
        for (int mh = 0; mh < 2; mh++) {
            uint32_t ah[2][4], al[2][4];
#pragma unroll
            for (int mi = 0; mi < 2; mi++) {
                int mt = mh * 2 + mi;
                uint32_t off = sw32((wm * 64 + mt * 16 + a_r) * 32 + a_k * 2);
                ldsm4(ah[mi][0], ah[mi][1], ah[mi][2], ah[mi][3], uA + off);
                ldsm4(al[mi][0], al[mi][1], al[mi][2], al[mi][3], uA + 4096 + off);
            }
#pragma unroll
            for (int mi = 0; mi < 2; mi++)
#pragma unroll
                for (int nt = 0; nt < 4; nt++) {
                    uint32_t b0h = bh[nt >> 1][(nt & 1) * 2];
                    uint32_t b1h = bh[nt >> 1][(nt & 1) * 2 + 1];
                    uint32_t b0l = bl[nt >> 1][(nt & 1) * 2];
                    uint32_t b1l = bl[nt >> 1][(nt & 1) * 2 + 1];
                    float* a4 = acc[mh * 2 + mi][nt];
                    mma_bf16(a4, ah[mi], b0h, b1h);   // Ah*Bh
                    mma_bf16(a4, al[mi], b0h, b1h);   // Al*Bh
                    mma_bf16(a4, ah[mi], b0l, b1l);   // Ah*Bl
                }
        }
    }
#undef ISSUE_STAGE
    __syncthreads();

    // ---- epilogue: add bias, write H, accumulate per-column stats ----
#pragma unroll
    for (int nt = 0; nt < 4; nt++) {
        int c = col0 + wn * 32 + nt * 8 + (lane & 3) * 2;
        float b0 = bias[c], b1 = bias[c + 1];
        float s0 = 0.f, s1 = 0.f, q0 = 0.f, q1 = 0.f;
#pragma unroll
        for (int mt = 0; mt < 4; mt++) {
            int r0 = row0 + wm * 64 + mt * 16 + (lane >> 2);
            float h0 = acc[mt][nt][0] + b0;
            float h1 = acc[mt][nt][1] + b1;
            float h2 = acc[mt][nt][2] + b0;
            float h3 = acc[mt][nt][3] + b1;
            *(float2*)&H[(size_t)r0 * 256 + c] = make_float2(h0, h1);
            *(float2*)&H[(size_t)(r0 + 8) * 256 + c] = make_float2(h2, h3);
            s0 += h0 + h2;  s1 += h1 + h3;
            q0 += h0 * h0 + h2 * h2;
            q1 += h1 * h1 + h3 * h3;
        }
#pragma unroll
        for (int off = 4; off < 32; off <<= 1) {
            s0 += __shfl_xor_sync(0xFFFFFFFFu, s0, off);
            s1 += __shfl_xor_sync(0xFFFFFFFFu, s1, off);
            q0 += __shfl_xor_sync(0xFFFFFFFFu, q0, off);
            q1 += __shfl_xor_sync(0xFFFFFFFFu, q1, off);
        }
        if (lane < 4) {
            int cl = wn * 32 + nt * 8 + lane * 2;
            sm_s[wm][cl] = s0;  sm_s[wm][cl + 1] = s1;
            sm_q[wm][cl] = q0;  sm_q[wm][cl + 1] = q1;
        }
    }
    __syncthreads();
    if (tid < 128) {
        g_psum[(col0 + tid) * 484 + blockIdx.y]   = sm_s[0][tid] + sm_s[1][tid];
        g_psumsq[(col0 + tid) * 484 + blockIdx.y] = sm_q[0][tid] + sm_q[1][tid];
    }
}

// ---------------- kernel 4: finalize BN affine (one block per column, coalesced) -----------
__global__ void bn_finalize_kernel(const float* __restrict__ gam,
                                   const float* __restrict__ beta,
                                   int M, int NB) {
    const int col = blockIdx.x;
    const int t = threadIdx.x;
    float s = 0.f, ss = 0.f;
    for (int i = t; i < NB; i += 128) {
        s  += g_psum[col * 484 + i];
        ss += g_psumsq[col * 484 + i];
    }
    __shared__ float shs[128], shq[128];
    shs[t] = s; shq[t] = ss;
    __syncthreads();
    for (int o = 64; o > 0; o >>= 1) {
        if (t < o) { shs[t] += shs[t + o]; shq[t] += shq[t + o]; }
        __syncthreads();
    }
    if (t == 0) {
        float inv_m = 1.f / (float)M;
        float mu  = shs[0] * inv_m;
        float var = shq[0] * inv_m - mu * mu;
        float inv = rsqrtf(var + EPS);
        float sc  = gam[col] * inv;
        g_scale[col] = sc;
        g_shift[col] = beta[col] - mu * sc;
    }
}

// ---------------- kernel 5: out = relu(bn(H3)) @ fc_w + fc_b  ([512,256]@[256,47]) ---------
__global__ void fc_kernel(const float* __restrict__ Hx, const float* __restrict__ W,
                          const float* __restrict__ b, float* __restrict__ out) {
    __shared__ float xs[256];
    const int row = blockIdx.x;
    const int t = threadIdx.x;
    xs[t] = fmaxf(0.f, Hx[row * 256 + t] * g_scale[t] + g_shift[t]);
    __syncthreads();
    if (t < 47) {
        float acc = b[t];
#pragma unroll 8
        for (int k = 0; k < 256; k++) acc += xs[k] * W[k * 47 + t];
        out[row * 47 + t] = acc;
    }
}

// ---------------- host ----------------
extern "C" void kernel_launch(void* const* d_in, const int* in_sizes, int n_in,
                              void* d_out, int out_size) {
    const bool dict_order = (in_sizes[4] == 65536);

    const float* x_feat = (const float*)d_in[0];
    const int *src[3], *tlid[3];
    const float *Wl[3], *Wr[3], *bb[3], *gam[3], *bet[3];
    if (dict_order) {
        for (int i = 0; i < 3; i++) {
            int base = 1 + i * 8;
            src[i]  = (const int*)d_in[base + 0];
            tlid[i] = (const int*)d_in[base + 2];
            Wl[i]   = (const float*)d_in[base + 3];
            Wr[i]   = (const float*)d_in[base + 4];
            bb[i]   = (const float*)d_in[base + 5];
            gam[i]  = (const float*)d_in[base + 6];
            bet[i]  = (const float*)d_in[base + 7];
        }
    } else {
        for (int i = 0; i < 3; i++) {
            src[i]  = (const int*)d_in[1 + i * 3];
            tlid[i] = (const int*)d_in[3 + i * 3];
            Wl[i]   = (const float*)d_in[10 + i * 5];
            Wr[i]   = (const float*)d_in[11 + i * 5];
            bb[i]   = (const float*)d_in[12 + i * 5];
            gam[i]  = (const float*)d_in[13 + i * 5];
            bet[i]  = (const float*)d_in[14 + i * 5];
        }
    }
    const float* fc_w = (const float*)d_in[25];
    const float* fc_b = (const float*)d_in[26];
    float* out = (float*)d_out;

    __nv_bfloat16 *Ahp, *Alp, *Bhp, *Blp;
    float *hb;
    cudaGetSymbolAddress((void**)&Ahp, g_Ah);
    cudaGetSymbolAddress((void**)&Alp, g_Al);
    cudaGetSymbolAddress((void**)&Bhp, g_Bh);
    cudaGetSymbolAddress((void**)&Blp, g_Bl);
    cudaGetSymbolAddress((void**)&hb,  g_h);

    const int NT[3] = {61952, 5632, 512};

    // Order chosen so gemm_mma_kernel (layer 0) is launch index 3 (profiler target):
    // conv_w0(0), gather0(1), conv_w1(2), gemm0(3), bnfin0(4), conv_w2(5), ...
    conv_w_kernel<<<512, 256>>>(Wl[0], Wr[0], Bhp, Blp);
    gather_mean_kernel<<<NT[0] / 4, 256>>>(x_feat, src[0], tlid[0], Ahp, Alp, 0);
    conv_w_kernel<<<512, 256>>>(Wl[1], Wr[1], Bhp + 131072, Blp + 131072);
    {
        dim3 gdim(2, NT[0] / 128);
        gemm_mma_kernel<<<gdim, 256>>>(Ahp, Alp, Bhp, Blp, bb[0], hb);
    }
    bn_finalize_kernel<<<256, 128>>>(gam[0], bet[0], NT[0], NT[0] / 128);
    conv_w_kernel<<<512, 256>>>(Wl[2], Wr[2], Bhp + 2 * 131072, Blp + 2 * 131072);

    for (int i = 1; i < 3; i++) {
        const int T = NT[i];
        gather_mean_kernel<<<T / 4, 256>>>(hb, src[i], tlid[i], Ahp, Alp, 1);
        dim3 gdim(2, T / 128);
        gemm_mma_kernel<<<gdim, 256>>>(Ahp, Alp, Bhp + i * 131072, Blp + i * 131072,
                                       bb[i], hb);
        bn_finalize_kernel<<<256, 128>>>(gam[i], bet[i], T, T / 128);
    }
    fc_kernel<<<512, 256>>>(hb, fc_w, fc_b, out);
}